// round 1
// baseline (speedup 1.0000x reference)
#include <cuda_runtime.h>

// ---------------- problem constants ----------------
#define NIMG 8
#define NC   32
#define NV   128
#define HH   128
#define WW   128
#define CIN  64
#define CC   65           // concat channels (scattered + feature)
#define CMID 256
#define HP   130          // padded
#define WP   130
#define KTOT 585          // 9 * 65
#define KCHUNK 13
#define NCHUNK 45         // 585 / 13

// ---------------- scratch (device globals, no runtime alloc) ----------------
__device__ float g_Fx[NC * NV * WW];                 // [c][v][x], includes 1/(2pi)
__device__ float g_Fy[NC * NV * HH];                 // [c][v][y]
__device__ float g_Xp[NIMG * CC * HP * WP];          // zero-padded concat input
__device__ float g_wT[KTOT * CMID];                  // w1 transposed: [k][m], k=(ky*3+kx)*65+ci
__device__ int   g_batch[NC];

// ---------------- batch_ind dtype detection (int32 vs int64) ----------------
__global__ void k_batch(const int* bi) {
    __shared__ int s_is64;
    if (threadIdx.x == 0) {
        int is64 = 1;
        // If the buffer is really int64 little-endian with values in [0,8),
        // every odd 32-bit word of the first 32 words is zero.
        #pragma unroll
        for (int i = 0; i < 16; i++)
            if (bi[2 * i + 1] != 0) is64 = 0;
        s_is64 = is64;
    }
    __syncthreads();
    int t = threadIdx.x;
    if (t < NC) g_batch[t] = s_is64 ? bi[2 * t] : bi[t];
}

// ---------------- separable Gaussian tables ----------------
__global__ void k_tables(const float* __restrict__ contour) {
    int v = blockIdx.x;   // 0..127
    int c = blockIdx.y;   // 0..31
    int t = threadIdx.x;  // 0..127 (coordinate)
    float cx = contour[(c * NV + v) * 2 + 0] * 0.25f;
    float cy = contour[(c * NV + v) * 2 + 1] * 0.25f;
    float dx = (float)t - cx;
    float dy = (float)t - cy;
    const float INV2PI = 0.15915494309189535f;
    g_Fx[(c * NV + v) * WW + t] = INV2PI * __expf(-0.5f * dx * dx);
    g_Fy[(c * NV + v) * HH + t] = __expf(-0.5f * dy * dy);
}

// ---------------- zero padded input ----------------
__global__ void k_zero() {
    const int n4 = (NIMG * CC * HP * WP) / 4;   // divisible by 4
    float4* p = (float4*)g_Xp;
    float4 z = make_float4(0.f, 0.f, 0.f, 0.f);
    for (int i = blockIdx.x * blockDim.x + threadIdx.x; i < n4;
         i += gridDim.x * blockDim.x)
        p[i] = z;
}

// ---------------- copy feature into padded buffer (channels 1..64) ----------------
__global__ void k_fill(const float* __restrict__ feat) {
    int x  = threadIdx.x;    // 0..127
    int y  = blockIdx.x;     // 0..127
    int ci = blockIdx.y;     // 0..63
    int n  = blockIdx.z;     // 0..7
    float v = feat[((n * CIN + ci) * HH + y) * WW + x];
    g_Xp[((n * CC + (ci + 1)) * HP + (y + 1)) * WP + (x + 1)] = v;
}

// ---------------- scattered = segment_sum of contour maps ----------------
// block: n = blockIdx.y, y0 = blockIdx.x * 8 ; 128 threads over x; acc[8] rows
__global__ void k_scatter(float* __restrict__ out_scat) {
    int n  = blockIdx.y;
    int y0 = blockIdx.x * 8;
    int x  = threadIdx.x;

    __shared__ float s_fy[NV][8];
    float acc[8];
    #pragma unroll
    for (int r = 0; r < 8; r++) acc[r] = 0.f;

    for (int c = 0; c < NC; c++) {
        if (g_batch[c] != n) continue;      // uniform across block
        __syncthreads();
        for (int idx = x; idx < NV * 8; idx += 128) {
            int v = idx >> 3, r = idx & 7;
            s_fy[v][r] = g_Fy[(c * NV + v) * HH + (y0 + r)];
        }
        __syncthreads();
        const float* fxp = &g_Fx[(c * NV) * WW + x];
        #pragma unroll 4
        for (int v = 0; v < NV; v++) {
            float fx = fxp[v * WW];
            #pragma unroll
            for (int r = 0; r < 8; r++) acc[r] += fx * s_fy[v][r];
        }
    }
    #pragma unroll
    for (int r = 0; r < 8; r++) {
        float val = acc[r];
        out_scat[(n * HH + (y0 + r)) * WW + x] = val;
        g_Xp[((n * CC + 0) * HP + (y0 + r + 1)) * WP + (x + 1)] = val;
    }
}

// ---------------- transpose w1 -> wT[k][m] ----------------
__global__ void k_wt(const float* __restrict__ w1) {
    int k = blockIdx.x;      // 0..584
    int m = threadIdx.x;     // 0..255
    int pos = k / 65, ci = k - pos * 65;
    int ky = pos / 3, kx = pos - ky * 3;
    g_wT[k * CMID + m] = w1[((m * CC + ci) * 3 + ky) * 3 + kx];
}

// ---------------- fused conv3x3(65->256)+bias+relu then conv1x1(256->2)+bias ----
// block tile: 64 pixels (32 wide x 2 high) x 256 channels; 256 threads
// per-thread micro-tile 8px x 8ch; K = 585 chunked by 13.
__global__ void __launch_bounds__(256) k_conv(const float* __restrict__ b1,
                                              const float* __restrict__ w2,
                                              const float* __restrict__ b2,
                                              float* __restrict__ outp) {
    int n  = blockIdx.z;
    int x0 = blockIdx.x * 32;
    int y0 = blockIdx.y * 2;
    int tid = threadIdx.x;
    int cg = tid & 31;     // channel group: channels cg*8 .. cg*8+7
    int pg = tid >> 5;     // pixel group (== warp id): pixels pg*8 .. pg*8+7

    __shared__ float s_in[KCHUNK][64];
    __shared__ float s_w[KCHUNK][CMID];
    __shared__ float s_w2[2][CMID];
    __shared__ float s_out[64][2];

    if (tid < 128) s_out[tid >> 1][tid & 1] = 0.f;
    for (int i = tid; i < 2 * CMID; i += 256) s_w2[i >> 8][i & 255] = w2[i];

    float bb[8];
    #pragma unroll
    for (int j = 0; j < 8; j++) bb[j] = b1[cg * 8 + j];

    float acc[8][8];
    #pragma unroll
    for (int i = 0; i < 8; i++)
        #pragma unroll
        for (int j = 0; j < 8; j++) acc[i][j] = bb[j];

    for (int ch = 0; ch < NCHUNK; ch++) {
        int k0 = ch * KCHUNK;
        __syncthreads();
        // stage input slice: 13 x 64
        for (int idx = tid; idx < KCHUNK * 64; idx += 256) {
            int kk = idx >> 6, p = idx & 63;
            int gk = k0 + kk;
            int pos = gk / 65, ci = gk - pos * 65;
            int ky = pos / 3, kx = pos - ky * 3;
            int px = p & 31, py = p >> 5;
            s_in[kk][p] = g_Xp[((n * CC + ci) * HP + (y0 + py + ky)) * WP +
                               (x0 + px + kx)];
        }
        // stage weight slice: 13 x 256 (coalesced from wT)
        for (int idx = tid; idx < KCHUNK * CMID; idx += 256) {
            int kk = idx >> 8, m = idx & 255;
            s_w[kk][m] = g_wT[(k0 + kk) * CMID + m];
        }
        __syncthreads();

        #pragma unroll
        for (int kk = 0; kk < KCHUNK; kk++) {
            float inr[8], wr[8];
            #pragma unroll
            for (int i = 0; i < 8; i++) inr[i] = s_in[kk][pg * 8 + i];
            #pragma unroll
            for (int j = 0; j < 8; j++) wr[j] = s_w[kk][cg * 8 + j];
            #pragma unroll
            for (int i = 0; i < 8; i++)
                #pragma unroll
                for (int j = 0; j < 8; j++) acc[i][j] += inr[i] * wr[j];
        }
    }

    // epilogue: relu then 1x1 conv partial sums, reduce over channel groups
    #pragma unroll
    for (int i = 0; i < 8; i++) {
        float p0 = 0.f, p1 = 0.f;
        #pragma unroll
        for (int j = 0; j < 8; j++) {
            int m = cg * 8 + j;
            float h = fmaxf(acc[i][j], 0.f);
            p0 += h * s_w2[0][m];
            p1 += h * s_w2[1][m];
        }
        int p = pg * 8 + i;
        atomicAdd(&s_out[p][0], p0);
        atomicAdd(&s_out[p][1], p1);
    }
    __syncthreads();
    if (tid < 128) {
        int p = tid >> 1, o = tid & 1;
        int px = p & 31, py = p >> 5;
        outp[((n * 2 + o) * HH + (y0 + py)) * WW + (x0 + px)] =
            s_out[p][o] + b2[o];
    }
}

// ---------------- launch ----------------
extern "C" void kernel_launch(void* const* d_in, const int* in_sizes, int n_in,
                              void* d_out, int out_size) {
    const float* contour = (const float*)d_in[0];
    const float* feature = (const float*)d_in[1];
    const int*   batchi  = (const int*)d_in[2];   // int32 or int64 (detected)
    const float* w1      = (const float*)d_in[3];
    const float* b1      = (const float*)d_in[4];
    const float* w2      = (const float*)d_in[5];
    const float* b2      = (const float*)d_in[6];
    float* out = (float*)d_out;
    float* out_scat = out + NIMG * 2 * HH * WW;   // scattered after conv output

    k_batch<<<1, 32>>>(batchi);
    k_tables<<<dim3(NV, NC), 128>>>(contour);
    k_zero<<<2048, 256>>>();
    k_fill<<<dim3(HH, CIN, NIMG), WW>>>(feature);
    k_scatter<<<dim3(HH / 8, NIMG), 128>>>(out_scat);
    k_wt<<<KTOT, CMID>>>(w1);
    k_conv<<<dim3(WW / 32, HH / 2, NIMG), 256>>>(b1, w2, b2, out);
}

// round 4
// speedup vs baseline: 2.6898x; 2.6898x over previous
#include <cuda_runtime.h>
#include <cuda_bf16.h>
#include <cstdint>

// ---------------- problem constants ----------------
#define NIMG 8
#define NC   32
#define NV   128
#define HH   128
#define WW   128
#define CIN  64
#define CC   65
#define CMID 256
#define HP   130
#define WP   130
#define KREAL 585          // 65 * 9, k = ci*9 + ky*3 + kx
#define KPAD  640
#define CHUNK 64
#define NCH   10

// ---------------- device scratch ----------------
__device__ float    g_Fx[NC * NV * WW];
__device__ float    g_Fy[NC * NV * HH];
__device__ uint32_t g_Xp2[NIMG * CC * HP * WP];   // packed (bf16 hi | bf16 lo<<16)
__device__ uint32_t g_wB[CMID * KPAD];            // packed weights, zero-padded K
__device__ int      g_batch[NC];

// ---------------- helpers ----------------
__device__ __forceinline__ uint32_t smem_u32(const void* p) {
    uint32_t a;
    asm("{ .reg .u64 t; cvta.to.shared.u64 t, %1; cvt.u32.u64 %0, t; }"
        : "=r"(a) : "l"(p));
    return a;
}
#define STS64(a, x, y) \
    asm volatile("st.shared.v2.b32 [%0], {%1, %2};" :: "r"(a), "r"(x), "r"(y) : "memory")

__device__ __forceinline__ void ldm_x4(uint32_t* r, uint32_t a) {
    asm volatile("ldmatrix.sync.aligned.m8n8.x4.shared.b16 {%0,%1,%2,%3}, [%4];"
        : "=r"(r[0]), "=r"(r[1]), "=r"(r[2]), "=r"(r[3]) : "r"(a));
}
__device__ __forceinline__ void ldm_x2(uint32_t* r, uint32_t a) {
    asm volatile("ldmatrix.sync.aligned.m8n8.x2.shared.b16 {%0,%1}, [%2];"
        : "=r"(r[0]), "=r"(r[1]) : "r"(a));
}
__device__ __forceinline__ void mma_bf16(float* d, const uint32_t* a, const uint32_t* b) {
    asm volatile("mma.sync.aligned.m16n8k16.row.col.f32.bf16.bf16.f32 "
        "{%0,%1,%2,%3}, {%4,%5,%6,%7}, {%8,%9}, {%0,%1,%2,%3};"
        : "+f"(d[0]), "+f"(d[1]), "+f"(d[2]), "+f"(d[3])
        : "r"(a[0]), "r"(a[1]), "r"(a[2]), "r"(a[3]), "r"(b[0]), "r"(b[1]));
}

__device__ __forceinline__ uint32_t pack2(float v) {
    __nv_bfloat16 h = __float2bfloat16(v);
    float r = v - __bfloat162float(h);
    __nv_bfloat16 l = __float2bfloat16(r);
    return (uint32_t)__bfloat16_as_ushort(h) |
           ((uint32_t)__bfloat16_as_ushort(l) << 16);
}

// ---------------- prep kernels ----------------
__global__ void k_batch(const int* bi) {
    __shared__ int s_is64;
    if (threadIdx.x == 0) {
        int is64 = 1;
        #pragma unroll
        for (int i = 0; i < 16; i++)
            if (bi[2 * i + 1] != 0) is64 = 0;
        s_is64 = is64;
    }
    __syncthreads();
    int t = threadIdx.x;
    if (t < NC) g_batch[t] = s_is64 ? bi[2 * t] : bi[t];
}

__global__ void k_tables(const float* __restrict__ contour) {
    int v = blockIdx.x, c = blockIdx.y, t = threadIdx.x;
    float cx = contour[(c * NV + v) * 2 + 0] * 0.25f;
    float cy = contour[(c * NV + v) * 2 + 1] * 0.25f;
    float dx = (float)t - cx, dy = (float)t - cy;
    const float INV2PI = 0.15915494309189535f;
    g_Fx[(c * NV + v) * WW + t] = INV2PI * __expf(-0.5f * dx * dx);
    g_Fy[(c * NV + v) * HH + t] = __expf(-0.5f * dy * dy);
}

__global__ void k_zero() {
    const int n4 = (NIMG * CC * HP * WP) / 4;
    uint4* p = (uint4*)g_Xp2;
    uint4 z = make_uint4(0, 0, 0, 0);
    for (int i = blockIdx.x * blockDim.x + threadIdx.x; i < n4;
         i += gridDim.x * blockDim.x) p[i] = z;
}

__global__ void k_fill(const float* __restrict__ feat) {
    int total = NIMG * CIN * HH * WW;
    for (int idx = blockIdx.x * blockDim.x + threadIdx.x; idx < total;
         idx += gridDim.x * blockDim.x) {
        int x = idx & 127;
        int y = (idx >> 7) & 127;
        int ci = (idx >> 14) & 63;
        int n = idx >> 20;
        g_Xp2[((n * CC + ci + 1) * HP + y + 1) * WP + x + 1] = pack2(feat[idx]);
    }
}

__global__ void k_scatter(float* __restrict__ out_scat) {
    int n = blockIdx.y, y0 = blockIdx.x * 8, x = threadIdx.x;
    __shared__ float s_fy[NV][8];
    float acc[8];
    #pragma unroll
    for (int r = 0; r < 8; r++) acc[r] = 0.f;
    for (int c = 0; c < NC; c++) {
        if (g_batch[c] != n) continue;
        __syncthreads();
        for (int idx = x; idx < NV * 8; idx += 128) {
            int v = idx >> 3, r = idx & 7;
            s_fy[v][r] = g_Fy[(c * NV + v) * HH + (y0 + r)];
        }
        __syncthreads();
        const float* fxp = &g_Fx[(c * NV) * WW + x];
        #pragma unroll 4
        for (int v = 0; v < NV; v++) {
            float fx = fxp[v * WW];
            #pragma unroll
            for (int r = 0; r < 8; r++) acc[r] += fx * s_fy[v][r];
        }
    }
    #pragma unroll
    for (int r = 0; r < 8; r++) {
        out_scat[(n * HH + y0 + r) * WW + x] = acc[r];
        g_Xp2[((n * CC + 0) * HP + (y0 + r + 1)) * WP + (x + 1)] = pack2(acc[r]);
    }
}

__global__ void k_wsplit(const float* __restrict__ w1) {
    int idx = blockIdx.x * blockDim.x + threadIdx.x;   // 256*640
    int m = idx / KPAD, k = idx - m * KPAD;
    float v = (k < KREAL) ? w1[m * KREAL + k] : 0.f;
    g_wB[idx] = pack2(v);
}

// ---------------- HMMA conv kernel (mma.sync bf16x3) ----------------
// CTA = one output row (n, y). D[128 px, 256 ch].
// smem: A_hi 16K | A_lo 16K | B_hi 32K | B_lo 32K  (single-buffered, 96 KB)
#define DSMEM_BYTES (98304 + 1024)

__global__ void __launch_bounds__(256, 1)
k_conv_mma(const float* __restrict__ b1, const float* __restrict__ w2,
           const float* __restrict__ b2, float* __restrict__ outp) {
    extern __shared__ char dsm[];
    __shared__ int   s_off[CHUNK];
    __shared__ float s_b1[CMID];
    __shared__ float s_w2[2 * CMID];
    __shared__ float s_part[HH * 2];

    const int tid  = threadIdx.x;
    const int wid  = tid >> 5;
    const int lane = tid & 31;
    const int gid  = lane >> 2;       // 0..7
    const int tq   = lane & 3;        // 0..3
    const int wm   = wid >> 2;        // 0..1 (px half)
    const int wn   = wid & 3;         // 0..3 (ch quarter)
    const int n = blockIdx.x >> 7;
    const int y = blockIdx.x & 127;

    uint32_t sb = smem_u32(dsm);
    const uint32_t aA = (sb + 1023u) & ~1023u;   // A_hi
    const uint32_t aB = aA + 32768u;             // B_hi (A_lo at aA+16384, B_lo at aB+32768)

    for (int i = tid; i < CMID; i += 256) s_b1[i] = b1[i];
    for (int i = tid; i < 2 * CMID; i += 256) s_w2[i] = w2[i];
    s_part[tid] = 0.f;

    float acc[4][8][4];
    #pragma unroll
    for (int mt = 0; mt < 4; mt++)
        #pragma unroll
        for (int nt = 0; nt < 8; nt++)
            #pragma unroll
            for (int r = 0; r < 4; r++) acc[mt][nt][r] = 0.f;

    const uint32_t xbase = (uint32_t)n * (CC * HP * WP) + (uint32_t)y * WP;

    // per-lane ldmatrix address components (row part precomputed)
    const int arow = (lane & 15);               // within m-tile
    const int acolsel = (lane >> 4) * 16;       // 0 or 16 bytes (k 0-7 / 8-15)
    const int brow = (lane & 7);
    const int bcolsel = ((lane >> 3) & 1) * 16;

    for (int c = 0; c < NCH; c++) {
        const int k0 = c * CHUNK;
        __syncthreads();
        if (tid < CHUNK) {
            int k = k0 + tid, off = -1;
            if (k < KREAL) {
                int ci = k / 9, pos = k - ci * 9;
                int ky = pos / 3, kx = pos - ky * 3;
                off = ci * (HP * WP) + ky * WP + kx;
            }
            s_off[tid] = off;
        }
        __syncthreads();

        // stage A: 128 px x 64 k (gather of packed words -> hi/lo tiles)
        #pragma unroll
        for (int it = tid; it < 2048; it += 256) {
            int x = it & 127;
            int g = it >> 7;                    // k-group of 4
            uint32_t bidx = xbase + (uint32_t)x;
            int o0 = s_off[g * 4 + 0], o1 = s_off[g * 4 + 1];
            int o2 = s_off[g * 4 + 2], o3 = s_off[g * 4 + 3];
            uint32_t w0 = (o0 >= 0) ? g_Xp2[bidx + o0] : 0u;
            uint32_t w1v = (o1 >= 0) ? g_Xp2[bidx + o1] : 0u;
            uint32_t w2v = (o2 >= 0) ? g_Xp2[bidx + o2] : 0u;
            uint32_t w3v = (o3 >= 0) ? g_Xp2[bidx + o3] : 0u;
            uint32_t h0 = __byte_perm(w0, w1v, 0x5410);
            uint32_t h1 = __byte_perm(w2v, w3v, 0x5410);
            uint32_t l0 = __byte_perm(w0, w1v, 0x7632);
            uint32_t l1 = __byte_perm(w2v, w3v, 0x7632);
            int rb = x * 128 + g * 8;
            int sw = rb ^ ((rb >> 3) & 0x70);
            STS64(aA + sw, h0, h1);
            STS64(aA + 16384 + sw, l0, l1);
        }
        // stage B: 256 ch x 64 k (contiguous)
        #pragma unroll
        for (int it = tid; it < 4096; it += 256) {
            int q = it & 15, m = it >> 4;
            const uint4 v = *(const uint4*)(g_wB + (size_t)m * KPAD + k0 + q * 4);
            uint32_t h0 = __byte_perm(v.x, v.y, 0x5410);
            uint32_t h1 = __byte_perm(v.z, v.w, 0x5410);
            uint32_t l0 = __byte_perm(v.x, v.y, 0x7632);
            uint32_t l1 = __byte_perm(v.z, v.w, 0x7632);
            int rb = m * 128 + q * 8;
            int sw = rb ^ ((rb >> 3) & 0x70);
            STS64(aB + sw, h0, h1);
            STS64(aB + 32768 + sw, l0, l1);
        }
        __syncthreads();

        // MMA: 4 k-steps of 16
        #pragma unroll
        for (int ks = 0; ks < 4; ks++) {
            const int kcol = ks * 32;           // byte col of k-step
            uint32_t Afrag[4][4];
            // pass 1: A_hi with B_hi and B_lo
            #pragma unroll
            for (int mt = 0; mt < 4; mt++) {
                int row = wm * 64 + mt * 16 + arow;
                int colb = kcol + acolsel;
                uint32_t ad = aA + (uint32_t)(row * 128 + (colb ^ ((row & 7) * 16)));
                ldm_x4(Afrag[mt], ad);
            }
            #pragma unroll
            for (int nt = 0; nt < 8; nt++) {
                int rowb = wn * 64 + nt * 8 + brow;
                int colb = kcol + bcolsel;
                uint32_t bd = aB + (uint32_t)(rowb * 128 + (colb ^ ((rowb & 7) * 16)));
                uint32_t Bh[2], Bl[2];
                ldm_x2(Bh, bd);
                ldm_x2(Bl, bd + 32768u);
                #pragma unroll
                for (int mt = 0; mt < 4; mt++) mma_bf16(acc[mt][nt], Afrag[mt], Bh);
                #pragma unroll
                for (int mt = 0; mt < 4; mt++) mma_bf16(acc[mt][nt], Afrag[mt], Bl);
            }
            // pass 2: A_lo with B_hi
            #pragma unroll
            for (int mt = 0; mt < 4; mt++) {
                int row = wm * 64 + mt * 16 + arow;
                int colb = kcol + acolsel;
                uint32_t ad = aA + 16384u + (uint32_t)(row * 128 + (colb ^ ((row & 7) * 16)));
                ldm_x4(Afrag[mt], ad);
            }
            #pragma unroll
            for (int nt = 0; nt < 8; nt++) {
                int rowb = wn * 64 + nt * 8 + brow;
                int colb = kcol + bcolsel;
                uint32_t bd = aB + (uint32_t)(rowb * 128 + (colb ^ ((rowb & 7) * 16)));
                uint32_t Bh[2];
                ldm_x2(Bh, bd);
                #pragma unroll
                for (int mt = 0; mt < 4; mt++) mma_bf16(acc[mt][nt], Afrag[mt], Bh);
            }
        }
    }
    __syncthreads();

    // epilogue: relu(D + b1) -> 1x1 conv to 2 channels, reduce across lanes/warps
    #pragma unroll
    for (int mt = 0; mt < 4; mt++) {
        #pragma unroll
        for (int half = 0; half < 2; half++) {
            float s0 = 0.f, s1 = 0.f;
            #pragma unroll
            for (int nt = 0; nt < 8; nt++) {
                int ch0 = wn * 64 + nt * 8 + tq * 2;
                float h0 = fmaxf(acc[mt][nt][half * 2 + 0] + s_b1[ch0], 0.f);
                float h1 = fmaxf(acc[mt][nt][half * 2 + 1] + s_b1[ch0 + 1], 0.f);
                s0 += h0 * s_w2[ch0] + h1 * s_w2[ch0 + 1];
                s1 += h0 * s_w2[CMID + ch0] + h1 * s_w2[CMID + ch0 + 1];
            }
            s0 += __shfl_xor_sync(0xffffffffu, s0, 1);
            s0 += __shfl_xor_sync(0xffffffffu, s0, 2);
            s1 += __shfl_xor_sync(0xffffffffu, s1, 1);
            s1 += __shfl_xor_sync(0xffffffffu, s1, 2);
            if (tq == 0) {
                int px = wm * 64 + mt * 16 + half * 8 + gid;
                atomicAdd(&s_part[px * 2 + 0], s0);
                atomicAdd(&s_part[px * 2 + 1], s1);
            }
        }
    }
    __syncthreads();
    {
        int px = tid >> 1, o = tid & 1;
        outp[((n * 2 + o) * HH + y) * WW + px] = s_part[px * 2 + o] + b2[o];
    }
}

// ---------------- launch ----------------
extern "C" void kernel_launch(void* const* d_in, const int* in_sizes, int n_in,
                              void* d_out, int out_size) {
    const float* contour = (const float*)d_in[0];
    const float* feature = (const float*)d_in[1];
    const int*   batchi  = (const int*)d_in[2];
    const float* w1      = (const float*)d_in[3];
    const float* b1      = (const float*)d_in[4];
    const float* w2      = (const float*)d_in[5];
    const float* b2      = (const float*)d_in[6];
    float* out = (float*)d_out;
    float* out_scat = out + NIMG * 2 * HH * WW;

    static int attr_set = 0;
    if (!attr_set) {
        cudaFuncSetAttribute(k_conv_mma,
                             cudaFuncAttributeMaxDynamicSharedMemorySize,
                             DSMEM_BYTES);
        attr_set = 1;
    }

    k_batch<<<1, 32>>>(batchi);
    k_tables<<<dim3(NV, NC), 128>>>(contour);
    k_zero<<<2048, 256>>>();
    k_fill<<<4096, 256>>>(feature);
    k_scatter<<<dim3(HH / 8, NIMG), 128>>>(out_scat);
    k_wsplit<<<CMID * KPAD / 256, 256>>>(w1);
    k_conv_mma<<<1024, 256, DSMEM_BYTES>>>(b1, w2, b2, out);
}

// round 5
// speedup vs baseline: 2.8230x; 1.0495x over previous
#include <cuda_runtime.h>
#include <cuda_bf16.h>
#include <cstdint>

// ---------------- problem constants ----------------
#define NIMG 8
#define NC   32
#define NV   128
#define HH   128
#define WW   128
#define CIN  64
#define CC   65
#define CMID 256
#define HP   130
#define WP   130
#define KREAL 585          // 65 * 9, k = ci*9 + ky*3 + kx
#define KPAD  640
#define CHUNK 64
#define NCH   10

// ---------------- device scratch ----------------
__device__ float    g_Fx[NC * NV * WW];
__device__ float    g_Fy[NC * NV * HH];
__device__ uint32_t g_Xp2[NIMG * CC * HP * WP];   // packed (bf16 hi | bf16 lo<<16)
__device__ uint4    g_wBh4[NCH * 2048];           // pre-swizzled hi weight planes (32KB/chunk)
__device__ uint4    g_wBl4[NCH * 2048];           // pre-swizzled lo weight planes
__device__ int      g_batch[NC];

// ---------------- helpers ----------------
__device__ __forceinline__ uint32_t smem_u32(const void* p) {
    uint32_t a;
    asm("{ .reg .u64 t; cvta.to.shared.u64 t, %1; cvt.u32.u64 %0, t; }"
        : "=r"(a) : "l"(p));
    return a;
}
#define STS64(a, x, y) \
    asm volatile("st.shared.v2.b32 [%0], {%1, %2};" :: "r"(a), "r"(x), "r"(y) : "memory")
#define STS128(a, v) \
    asm volatile("st.shared.v4.b32 [%0], {%1, %2, %3, %4};" \
                 :: "r"(a), "r"((v).x), "r"((v).y), "r"((v).z), "r"((v).w) : "memory")

__device__ __forceinline__ void ldm_x4(uint32_t* r, uint32_t a) {
    asm volatile("ldmatrix.sync.aligned.m8n8.x4.shared.b16 {%0,%1,%2,%3}, [%4];"
        : "=r"(r[0]), "=r"(r[1]), "=r"(r[2]), "=r"(r[3]) : "r"(a));
}
__device__ __forceinline__ void ldm_x2(uint32_t* r, uint32_t a) {
    asm volatile("ldmatrix.sync.aligned.m8n8.x2.shared.b16 {%0,%1}, [%2];"
        : "=r"(r[0]), "=r"(r[1]) : "r"(a));
}
__device__ __forceinline__ void mma_bf16(float* d, const uint32_t* a, const uint32_t* b) {
    asm volatile("mma.sync.aligned.m16n8k16.row.col.f32.bf16.bf16.f32 "
        "{%0,%1,%2,%3}, {%4,%5,%6,%7}, {%8,%9}, {%0,%1,%2,%3};"
        : "+f"(d[0]), "+f"(d[1]), "+f"(d[2]), "+f"(d[3])
        : "r"(a[0]), "r"(a[1]), "r"(a[2]), "r"(a[3]), "r"(b[0]), "r"(b[1]));
}

__device__ __forceinline__ uint32_t pack2(float v) {
    __nv_bfloat16 h = __float2bfloat16(v);
    float r = v - __bfloat162float(h);
    __nv_bfloat16 l = __float2bfloat16(r);
    return (uint32_t)__bfloat16_as_ushort(h) |
           ((uint32_t)__bfloat16_as_ushort(l) << 16);
}

// ---------------- prep kernels ----------------
__global__ void k_batch(const int* bi) {
    __shared__ int s_is64;
    if (threadIdx.x == 0) {
        int is64 = 1;
        #pragma unroll
        for (int i = 0; i < 16; i++)
            if (bi[2 * i + 1] != 0) is64 = 0;
        s_is64 = is64;
    }
    __syncthreads();
    int t = threadIdx.x;
    if (t < NC) g_batch[t] = s_is64 ? bi[2 * t] : bi[t];
}

__global__ void k_tables(const float* __restrict__ contour) {
    int v = blockIdx.x, c = blockIdx.y, t = threadIdx.x;
    float cx = contour[(c * NV + v) * 2 + 0] * 0.25f;
    float cy = contour[(c * NV + v) * 2 + 1] * 0.25f;
    float dx = (float)t - cx, dy = (float)t - cy;
    const float INV2PI = 0.15915494309189535f;
    g_Fx[(c * NV + v) * WW + t] = INV2PI * __expf(-0.5f * dx * dx);
    g_Fy[(c * NV + v) * HH + t] = __expf(-0.5f * dy * dy);
}

__global__ void k_zero() {
    const int n4 = (NIMG * CC * HP * WP) / 4;
    uint4* p = (uint4*)g_Xp2;
    uint4 z = make_uint4(0, 0, 0, 0);
    for (int i = blockIdx.x * blockDim.x + threadIdx.x; i < n4;
         i += gridDim.x * blockDim.x) p[i] = z;
}

__global__ void k_fill(const float* __restrict__ feat) {
    int total4 = (NIMG * CIN * HH * WW) / 4;
    for (int i4 = blockIdx.x * blockDim.x + threadIdx.x; i4 < total4;
         i4 += gridDim.x * blockDim.x) {
        int idx = i4 * 4;
        int x = idx & 127;
        int y = (idx >> 7) & 127;
        int ci = (idx >> 14) & 63;
        int n = idx >> 20;
        float4 v = *(const float4*)(feat + idx);
        uint32_t* dst = &g_Xp2[((n * CC + ci + 1) * HP + y + 1) * WP + x + 1];
        dst[0] = pack2(v.x);
        dst[1] = pack2(v.y);
        dst[2] = pack2(v.z);
        dst[3] = pack2(v.w);
    }
}

__global__ void k_scatter(float* __restrict__ out_scat) {
    int n = blockIdx.y, y0 = blockIdx.x * 8, x = threadIdx.x;
    __shared__ float s_fy[NV][8];
    float acc[8];
    #pragma unroll
    for (int r = 0; r < 8; r++) acc[r] = 0.f;
    for (int c = 0; c < NC; c++) {
        if (g_batch[c] != n) continue;
        __syncthreads();
        for (int idx = x; idx < NV * 8; idx += 128) {
            int v = idx >> 3, r = idx & 7;
            s_fy[v][r] = g_Fy[(c * NV + v) * HH + (y0 + r)];
        }
        __syncthreads();
        const float* fxp = &g_Fx[(c * NV) * WW + x];
        #pragma unroll 4
        for (int v = 0; v < NV; v++) {
            float fx = fxp[v * WW];
            #pragma unroll
            for (int r = 0; r < 8; r++) acc[r] += fx * s_fy[v][r];
        }
    }
    #pragma unroll
    for (int r = 0; r < 8; r++) {
        out_scat[(n * HH + y0 + r) * WW + x] = acc[r];
        g_Xp2[((n * CC + 0) * HP + (y0 + r + 1)) * WP + (x + 1)] = pack2(acc[r]);
    }
}

// weights pre-split into hi/lo bf16, stored in final swizzled smem byte layout
__global__ void k_wsplit(const float* __restrict__ w1) {
    int idx = blockIdx.x * blockDim.x + threadIdx.x;   // NCH*256*64
    int c = idx >> 14;
    int r = idx & 16383;
    int m = r >> 6, q = r & 63;
    int kg = c * CHUNK + q;
    float v = (kg < KREAL) ? w1[m * KREAL + kg] : 0.f;
    __nv_bfloat16 h = __float2bfloat16(v);
    float res = v - __bfloat162float(h);
    __nv_bfloat16 l = __float2bfloat16(res);
    int off = m * 128 + q * 2;
    int sw = off ^ ((off >> 3) & 0x70);
    ((uint16_t*)g_wBh4)[c * 16384 + (sw >> 1)] = __bfloat16_as_ushort(h);
    ((uint16_t*)g_wBl4)[c * 16384 + (sw >> 1)] = __bfloat16_as_ushort(l);
}

// ---------------- HMMA conv kernel (double-buffered bf16x3) ----------------
// CTA = one output row (n, y). D[128 px, 256 ch].
// dyn smem: A0 32K | A1 32K | B0 64K | B1 64K = 192KB
#define DSMEM_BYTES (196608 + 1024)

__global__ void __launch_bounds__(256, 1)
k_conv_mma(const float* __restrict__ b1, const float* __restrict__ w2,
           const float* __restrict__ b2, float* __restrict__ outp) {
    extern __shared__ char dsm[];
    __shared__ int   s_off[KPAD];
    __shared__ float s_b1[CMID];
    __shared__ float s_w2[2 * CMID];
    __shared__ float s_part[HH * 2];

    const int tid  = threadIdx.x;
    const int wid  = tid >> 5;
    const int lane = tid & 31;
    const int gid  = lane >> 2;       // 0..7
    const int tq   = lane & 3;        // 0..3
    const int wm   = wid >> 2;        // 0..1 (px half)
    const int wn   = wid & 3;         // 0..3 (ch quarter)
    const int n = blockIdx.x >> 7;
    const int y = blockIdx.x & 127;

    uint32_t sb = smem_u32(dsm);
    const uint32_t base = (sb + 1023u) & ~1023u;
    // A buffers: base + buf*32768 (hi), +16384 (lo)
    // B buffers: base + 65536 + buf*65536 (hi), +32768 (lo)

    for (int i = tid; i < CMID; i += 256) s_b1[i] = b1[i];
    for (int i = tid; i < 2 * CMID; i += 256) s_w2[i] = w2[i];
    s_part[tid] = 0.f;
    // precompute all gather offsets once
    for (int k = tid; k < KPAD; k += 256) {
        int off = -1;
        if (k < KREAL) {
            int ci = k / 9, pos = k - ci * 9;
            int ky = pos / 3, kx = pos - ky * 3;
            off = ci * (HP * WP) + ky * WP + kx;
        }
        s_off[k] = off;
    }

    float acc[4][8][4];
    #pragma unroll
    for (int mt = 0; mt < 4; mt++)
        #pragma unroll
        for (int nt = 0; nt < 8; nt++)
            #pragma unroll
            for (int r = 0; r < 4; r++) acc[mt][nt][r] = 0.f;

    const uint32_t xbase = (uint32_t)n * (CC * HP * WP) + (uint32_t)y * WP;

    const int arow = (lane & 15);
    const int acolsel = (lane >> 4) * 16;
    const int brow = (lane & 7);
    const int bcolsel = ((lane >> 3) & 1) * 16;

    // staging lambdas (macros to keep everything inlined)
    const int sx = tid & 127;          // fixed px per thread for A staging
    const int sg0 = tid >> 7;          // first k-group

#define STAGE_A(k0, aA)                                                        \
    do {                                                                       \
        _Pragma("unroll")                                                      \
        for (int i = 0; i < 8; i++) {                                          \
            int g = sg0 + 2 * i;                                               \
            uint32_t bidx = xbase + (uint32_t)sx;                              \
            int o0 = s_off[(k0) + g * 4 + 0], o1 = s_off[(k0) + g * 4 + 1];    \
            int o2 = s_off[(k0) + g * 4 + 2], o3 = s_off[(k0) + g * 4 + 3];    \
            uint32_t w0 = (o0 >= 0) ? g_Xp2[bidx + o0] : 0u;                   \
            uint32_t w1v = (o1 >= 0) ? g_Xp2[bidx + o1] : 0u;                  \
            uint32_t w2v = (o2 >= 0) ? g_Xp2[bidx + o2] : 0u;                  \
            uint32_t w3v = (o3 >= 0) ? g_Xp2[bidx + o3] : 0u;                  \
            uint32_t h0 = __byte_perm(w0, w1v, 0x5410);                        \
            uint32_t h1 = __byte_perm(w2v, w3v, 0x5410);                       \
            uint32_t l0 = __byte_perm(w0, w1v, 0x7632);                        \
            uint32_t l1 = __byte_perm(w2v, w3v, 0x7632);                       \
            int rb = sx * 128 + g * 8;                                         \
            int sw = rb ^ ((rb >> 3) & 0x70);                                  \
            STS64((aA) + sw, h0, h1);                                          \
            STS64((aA) + 16384 + sw, l0, l1);                                  \
        }                                                                      \
    } while (0)

#define STAGE_B(c, aB)                                                         \
    do {                                                                       \
        const uint4* srcH = g_wBh4 + (c) * 2048;                               \
        const uint4* srcL = g_wBl4 + (c) * 2048;                               \
        _Pragma("unroll")                                                      \
        for (int i = 0; i < 8; i++) {                                          \
            int gi = tid + i * 256;                                            \
            uint4 vh = srcH[gi];                                               \
            uint4 vl = srcL[gi];                                               \
            STS128((aB) + gi * 16, vh);                                        \
            STS128((aB) + 32768 + gi * 16, vl);                                \
        }                                                                      \
    } while (0)

    __syncthreads();
    // prologue: stage chunk 0 into buffer 0
    STAGE_A(0, base);
    STAGE_B(0, base + 65536u);
    __syncthreads();

    for (int c = 0; c < NCH; c++) {
        const int cur = c & 1;
        const uint32_t aA = base + (uint32_t)cur * 32768u;
        const uint32_t aB = base + 65536u + (uint32_t)cur * 65536u;

        // stage next chunk into the other buffer (free since MMA c-1 done)
        if (c < NCH - 1) {
            const int nxt = cur ^ 1;
            STAGE_A((c + 1) * CHUNK, base + (uint32_t)nxt * 32768u);
            STAGE_B(c + 1, base + 65536u + (uint32_t)nxt * 65536u);
        }

        // MMA on current buffer; last chunk has only 9 real k -> 1 k-step
        const int nks = (c == NCH - 1) ? 1 : 4;
        #pragma unroll
        for (int ks = 0; ks < 4; ks++) {
            if (ks >= nks) break;
            const int kcol = ks * 32;
            uint32_t Afrag[4][4];
            #pragma unroll
            for (int mt = 0; mt < 4; mt++) {
                int row = wm * 64 + mt * 16 + arow;
                int colb = kcol + acolsel;
                uint32_t ad = aA + (uint32_t)(row * 128 + (colb ^ ((row & 7) * 16)));
                ldm_x4(Afrag[mt], ad);
            }
            #pragma unroll
            for (int nt = 0; nt < 8; nt++) {
                int rowb = wn * 64 + nt * 8 + brow;
                int colb = kcol + bcolsel;
                uint32_t bd = aB + (uint32_t)(rowb * 128 + (colb ^ ((rowb & 7) * 16)));
                uint32_t Bh[2], Bl[2];
                ldm_x2(Bh, bd);
                ldm_x2(Bl, bd + 32768u);
                #pragma unroll
                for (int mt = 0; mt < 4; mt++) mma_bf16(acc[mt][nt], Afrag[mt], Bh);
                #pragma unroll
                for (int mt = 0; mt < 4; mt++) mma_bf16(acc[mt][nt], Afrag[mt], Bl);
            }
            #pragma unroll
            for (int mt = 0; mt < 4; mt++) {
                int row = wm * 64 + mt * 16 + arow;
                int colb = kcol + acolsel;
                uint32_t ad = aA + 16384u + (uint32_t)(row * 128 + (colb ^ ((row & 7) * 16)));
                ldm_x4(Afrag[mt], ad);
            }
            #pragma unroll
            for (int nt = 0; nt < 8; nt++) {
                int rowb = wn * 64 + nt * 8 + brow;
                int colb = kcol + bcolsel;
                uint32_t bd = aB + (uint32_t)(rowb * 128 + (colb ^ ((rowb & 7) * 16)));
                uint32_t Bh[2];
                ldm_x2(Bh, bd);
                #pragma unroll
                for (int mt = 0; mt < 4; mt++) mma_bf16(acc[mt][nt], Afrag[mt], Bh);
            }
        }
        __syncthreads();   // staging c+1 done + all warps past MMA c
    }

    // epilogue: relu(D + b1) -> 1x1 conv to 2 channels
    #pragma unroll
    for (int mt = 0; mt < 4; mt++) {
        #pragma unroll
        for (int half = 0; half < 2; half++) {
            float s0 = 0.f, s1 = 0.f;
            #pragma unroll
            for (int nt = 0; nt < 8; nt++) {
                int ch0 = wn * 64 + nt * 8 + tq * 2;
                float h0 = fmaxf(acc[mt][nt][half * 2 + 0] + s_b1[ch0], 0.f);
                float h1 = fmaxf(acc[mt][nt][half * 2 + 1] + s_b1[ch0 + 1], 0.f);
                s0 += h0 * s_w2[ch0] + h1 * s_w2[ch0 + 1];
                s1 += h0 * s_w2[CMID + ch0] + h1 * s_w2[CMID + ch0 + 1];
            }
            s0 += __shfl_xor_sync(0xffffffffu, s0, 1);
            s0 += __shfl_xor_sync(0xffffffffu, s0, 2);
            s1 += __shfl_xor_sync(0xffffffffu, s1, 1);
            s1 += __shfl_xor_sync(0xffffffffu, s1, 2);
            if (tq == 0) {
                int px = wm * 64 + mt * 16 + half * 8 + gid;
                atomicAdd(&s_part[px * 2 + 0], s0);
                atomicAdd(&s_part[px * 2 + 1], s1);
            }
        }
    }
    __syncthreads();
    {
        int px = tid >> 1, o = tid & 1;
        outp[((n * 2 + o) * HH + y) * WW + px] = s_part[px * 2 + o] + b2[o];
    }
}

// ---------------- launch ----------------
extern "C" void kernel_launch(void* const* d_in, const int* in_sizes, int n_in,
                              void* d_out, int out_size) {
    const float* contour = (const float*)d_in[0];
    const float* feature = (const float*)d_in[1];
    const int*   batchi  = (const int*)d_in[2];
    const float* w1      = (const float*)d_in[3];
    const float* b1      = (const float*)d_in[4];
    const float* w2      = (const float*)d_in[5];
    const float* b2      = (const float*)d_in[6];
    float* out = (float*)d_out;
    float* out_scat = out + NIMG * 2 * HH * WW;

    static int attr_set = 0;
    if (!attr_set) {
        cudaFuncSetAttribute(k_conv_mma,
                             cudaFuncAttributeMaxDynamicSharedMemorySize,
                             DSMEM_BYTES);
        attr_set = 1;
    }

    k_batch<<<1, 32>>>(batchi);
    k_tables<<<dim3(NV, NC), 128>>>(contour);
    k_zero<<<2048, 256>>>();
    k_fill<<<2048, 256>>>(feature);
    k_scatter<<<dim3(HH / 8, NIMG), 128>>>(out_scat);
    k_wsplit<<<NCH * 16384 / 256, 256>>>(w1);
    k_conv_mma<<<1024, 256, DSMEM_BYTES>>>(b1, w2, b2, out);
}

// round 6
// speedup vs baseline: 3.3741x; 1.1952x over previous
#include <cuda_runtime.h>
#include <cuda_fp16.h>
#include <cstdint>

// ---------------- problem constants ----------------
#define NIMG 8
#define NC   32
#define NV   128
#define HH   128
#define WW   128
#define CIN  64
#define CC   65
#define CMID 256
#define HP   130
#define WP   130
#define KREAL 585          // 65 * 9, k = ci*9 + ky*3 + kx
#define KPAD  640
#define CHUNK 64
#define NCH   10

// ---------------- device scratch ----------------
__device__ float    g_Fx[NC * NV * WW];
__device__ float    g_Fy[NC * NV * HH];
__device__ uint32_t g_Xp2[NIMG * CC * HP * WP];   // packed (fp16 hi | fp16 lo<<16)
__device__ uint4    g_wBh4[NCH * 2048];           // pre-swizzled hi weight planes (32KB/chunk)
__device__ uint4    g_wBl4[NCH * 2048];           // pre-swizzled lo weight planes
__device__ int      g_batch[NC];

// ---------------- helpers ----------------
__device__ __forceinline__ uint32_t smem_u32(const void* p) {
    uint32_t a;
    asm("{ .reg .u64 t; cvta.to.shared.u64 t, %1; cvt.u32.u64 %0, t; }"
        : "=r"(a) : "l"(p));
    return a;
}
#define STS64(a, x, y) \
    asm volatile("st.shared.v2.b32 [%0], {%1, %2};" :: "r"(a), "r"(x), "r"(y) : "memory")
#define STS128(a, v) \
    asm volatile("st.shared.v4.b32 [%0], {%1, %2, %3, %4};" \
                 :: "r"(a), "r"((v).x), "r"((v).y), "r"((v).z), "r"((v).w) : "memory")

__device__ __forceinline__ void ldm_x4(uint32_t* r, uint32_t a) {
    asm volatile("ldmatrix.sync.aligned.m8n8.x4.shared.b16 {%0,%1,%2,%3}, [%4];"
        : "=r"(r[0]), "=r"(r[1]), "=r"(r[2]), "=r"(r[3]) : "r"(a));
}
__device__ __forceinline__ void ldm_x2(uint32_t* r, uint32_t a) {
    asm volatile("ldmatrix.sync.aligned.m8n8.x2.shared.b16 {%0,%1}, [%2];"
        : "=r"(r[0]), "=r"(r[1]) : "r"(a));
}
__device__ __forceinline__ void mma_fp16(float* d, const uint32_t* a, const uint32_t* b) {
    asm volatile("mma.sync.aligned.m16n8k16.row.col.f32.f16.f16.f32 "
        "{%0,%1,%2,%3}, {%4,%5,%6,%7}, {%8,%9}, {%0,%1,%2,%3};"
        : "+f"(d[0]), "+f"(d[1]), "+f"(d[2]), "+f"(d[3])
        : "r"(a[0]), "r"(a[1]), "r"(a[2]), "r"(a[3]), "r"(b[0]), "r"(b[1]));
}

__device__ __forceinline__ uint32_t pack2(float v) {
    __half h = __float2half_rn(v);
    float r = v - __half2float(h);
    __half l = __float2half_rn(r);
    return (uint32_t)__half_as_ushort(h) |
           ((uint32_t)__half_as_ushort(l) << 16);
}

// ---------------- prep kernel 1: tables + batch ----------------
__global__ void k_prep1(const float* __restrict__ contour, const int* bi) {
    int bid = blockIdx.x;
    if (bid < NV * NC) {
        int v = bid & 127, c = bid >> 7, t = threadIdx.x;
        float cx = contour[(c * NV + v) * 2 + 0] * 0.25f;
        float cy = contour[(c * NV + v) * 2 + 1] * 0.25f;
        float dx = (float)t - cx, dy = (float)t - cy;
        const float INV2PI = 0.15915494309189535f;
        g_Fx[(c * NV + v) * WW + t] = INV2PI * __expf(-0.5f * dx * dx);
        g_Fy[(c * NV + v) * HH + t] = __expf(-0.5f * dy * dy);
    } else {
        __shared__ int s_is64;
        if (threadIdx.x == 0) {
            int is64 = 1;
            #pragma unroll
            for (int i = 0; i < 16; i++)
                if (bi[2 * i + 1] != 0) is64 = 0;
            s_is64 = is64;
        }
        __syncthreads();
        int t = threadIdx.x;
        if (t < NC) g_batch[t] = s_is64 ? bi[2 * t] : bi[t];
    }
}

// ---------------- prep kernel 2: fill + frame-zero + weight split ----------------
#define FILL_BLOCKS 2048
#define FRAME_BLOCKS 1049
#define WS_BLOCKS 640
__global__ void k_prep2(const float* __restrict__ feat, const float* __restrict__ w1) {
    int bid = blockIdx.x;
    int tid = threadIdx.x;
    if (bid < FILL_BLOCKS) {
        // feature -> padded packed buffer (channels 1..64)
        const int total4 = (NIMG * CIN * HH * WW) / 4;
        for (int i4 = bid * 256 + tid; i4 < total4; i4 += FILL_BLOCKS * 256) {
            int idx = i4 * 4;
            int x = idx & 127;
            int y = (idx >> 7) & 127;
            int ci = (idx >> 14) & 63;
            int n = idx >> 20;
            float4 v = *(const float4*)(feat + idx);
            uint32_t* dst = &g_Xp2[((n * CC + ci + 1) * HP + y + 1) * WP + x + 1];
            dst[0] = pack2(v.x);
            dst[1] = pack2(v.y);
            dst[2] = pack2(v.z);
            dst[3] = pack2(v.w);
        }
    } else if (bid < FILL_BLOCKS + FRAME_BLOCKS) {
        // zero the 1-px frame of every (n, ch) plane
        const int total = NIMG * CC * 516;
        int idx = (bid - FILL_BLOCKS) * 256 + tid;
        if (idx < total) {
            int plane = idx / 516, e = idx - plane * 516;
            int r, cc;
            if (e < 130)      { r = 0;   cc = e; }
            else if (e < 260) { r = 129; cc = e - 130; }
            else if (e < 388) { r = 1 + (e - 260); cc = 0; }
            else              { r = 1 + (e - 388); cc = 129; }
            g_Xp2[plane * (HP * WP) + r * WP + cc] = 0u;
        }
    } else {
        // weight split (fp16 hi/lo, pre-swizzled)
        int idx = (bid - FILL_BLOCKS - FRAME_BLOCKS) * 256 + tid;   // < NCH*16384
        int c = idx >> 14;
        int r = idx & 16383;
        int m = r >> 6, q = r & 63;
        int kg = c * CHUNK + q;
        float v = (kg < KREAL) ? w1[m * KREAL + kg] : 0.f;
        __half h = __float2half_rn(v);
        float res = v - __half2float(h);
        __half l = __float2half_rn(res);
        int off = m * 128 + q * 2;
        int sw = off ^ ((off >> 3) & 0x70);
        ((uint16_t*)g_wBh4)[c * 16384 + (sw >> 1)] = __half_as_ushort(h);
        ((uint16_t*)g_wBl4)[c * 16384 + (sw >> 1)] = __half_as_ushort(l);
    }
}

// ---------------- scattered = segment_sum of contour maps ----------------
__global__ void k_scatter(float* __restrict__ out_scat) {
    int n = blockIdx.y, y0 = blockIdx.x * 8, x = threadIdx.x;
    __shared__ float s_fy[NV][8];
    float acc[8];
    #pragma unroll
    for (int r = 0; r < 8; r++) acc[r] = 0.f;
    for (int c = 0; c < NC; c++) {
        if (g_batch[c] != n) continue;
        __syncthreads();
        for (int idx = x; idx < NV * 8; idx += 128) {
            int v = idx >> 3, r = idx & 7;
            s_fy[v][r] = g_Fy[(c * NV + v) * HH + (y0 + r)];
        }
        __syncthreads();
        const float* fxp = &g_Fx[(c * NV) * WW + x];
        #pragma unroll 4
        for (int v = 0; v < NV; v++) {
            float fx = fxp[v * WW];
            #pragma unroll
            for (int r = 0; r < 8; r++) acc[r] += fx * s_fy[v][r];
        }
    }
    #pragma unroll
    for (int r = 0; r < 8; r++) {
        out_scat[(n * HH + y0 + r) * WW + x] = acc[r];
        g_Xp2[((n * CC + 0) * HP + (y0 + r + 1)) * WP + (x + 1)] = pack2(acc[r]);
    }
}

// ---------------- HMMA conv kernel (double-buffered, fp16 2-pass) ----------------
// CTA = one output row (n, y). D[128 px, 256 ch].
// dyn smem: A0 16K | A1 16K | B0 64K | B1 64K = 160KB
#define DSMEM_BYTES (163840 + 1024)

__global__ void __launch_bounds__(256, 1)
k_conv_mma(const float* __restrict__ b1, const float* __restrict__ w2,
           const float* __restrict__ b2, float* __restrict__ outp) {
    extern __shared__ char dsm[];
    __shared__ int   s_off[KPAD];
    __shared__ float s_b1[CMID];
    __shared__ float s_w2[2 * CMID];
    __shared__ float s_part[HH * 2];

    const int tid  = threadIdx.x;
    const int wid  = tid >> 5;
    const int lane = tid & 31;
    const int gid  = lane >> 2;       // 0..7
    const int tq   = lane & 3;        // 0..3
    const int wm   = wid >> 2;        // 0..1 (px half)
    const int wn   = wid & 3;         // 0..3 (ch quarter)
    const int n = blockIdx.x >> 7;
    const int y = blockIdx.x & 127;

    uint32_t sb = smem_u32(dsm);
    const uint32_t base = (sb + 1023u) & ~1023u;
    // A buffers: base + buf*16384
    // B buffers: base + 32768 + buf*65536 (hi), +32768 (lo)

    for (int i = tid; i < CMID; i += 256) s_b1[i] = b1[i];
    for (int i = tid; i < 2 * CMID; i += 256) s_w2[i] = w2[i];
    s_part[tid] = 0.f;
    for (int k = tid; k < KPAD; k += 256) {
        int off = -1;
        if (k < KREAL) {
            int ci = k / 9, pos = k - ci * 9;
            int ky = pos / 3, kx = pos - ky * 3;
            off = ci * (HP * WP) + ky * WP + kx;
        }
        s_off[k] = off;
    }

    float acc[4][8][4];
    #pragma unroll
    for (int mt = 0; mt < 4; mt++)
        #pragma unroll
        for (int nt = 0; nt < 8; nt++)
            #pragma unroll
            for (int r = 0; r < 4; r++) acc[mt][nt][r] = 0.f;

    const uint32_t xbase = (uint32_t)n * (CC * HP * WP) + (uint32_t)y * WP;

    const int arow = (lane & 15);
    const int acolsel = (lane >> 4) * 16;
    const int brow = (lane & 7);
    const int bcolsel = ((lane >> 3) & 1) * 16;

    const int sx = tid & 127;          // fixed px per thread for A staging
    const int sg0 = tid >> 7;          // first k-group

#define STAGE_A(k0, aA)                                                        \
    do {                                                                       \
        _Pragma("unroll")                                                      \
        for (int i = 0; i < 8; i++) {                                          \
            int g = sg0 + 2 * i;                                               \
            uint32_t bidx = xbase + (uint32_t)sx;                              \
            int o0 = s_off[(k0) + g * 4 + 0], o1 = s_off[(k0) + g * 4 + 1];    \
            int o2 = s_off[(k0) + g * 4 + 2], o3 = s_off[(k0) + g * 4 + 3];    \
            uint32_t w0 = (o0 >= 0) ? g_Xp2[bidx + o0] : 0u;                   \
            uint32_t w1v = (o1 >= 0) ? g_Xp2[bidx + o1] : 0u;                  \
            uint32_t w2v = (o2 >= 0) ? g_Xp2[bidx + o2] : 0u;                  \
            uint32_t w3v = (o3 >= 0) ? g_Xp2[bidx + o3] : 0u;                  \
            uint32_t h0 = __byte_perm(w0, w1v, 0x5410);                        \
            uint32_t h1 = __byte_perm(w2v, w3v, 0x5410);                       \
            int rb = sx * 128 + g * 8;                                         \
            int sw = rb ^ ((rb >> 3) & 0x70);                                  \
            STS64((aA) + sw, h0, h1);                                          \
        }                                                                      \
    } while (0)

#define STAGE_B(c, aB)                                                         \
    do {                                                                       \
        const uint4* srcH = g_wBh4 + (c) * 2048;                               \
        const uint4* srcL = g_wBl4 + (c) * 2048;                               \
        _Pragma("unroll")                                                      \
        for (int i = 0; i < 8; i++) {                                          \
            int gi = tid + i * 256;                                            \
            uint4 vh = srcH[gi];                                               \
            uint4 vl = srcL[gi];                                               \
            STS128((aB) + gi * 16, vh);                                        \
            STS128((aB) + 32768 + gi * 16, vl);                                \
        }                                                                      \
    } while (0)

    __syncthreads();
    STAGE_A(0, base);
    STAGE_B(0, base + 32768u);
    __syncthreads();

    for (int c = 0; c < NCH; c++) {
        const int cur = c & 1;
        const uint32_t aA = base + (uint32_t)cur * 16384u;
        const uint32_t aB = base + 32768u + (uint32_t)cur * 65536u;

        if (c < NCH - 1) {
            const int nxt = cur ^ 1;
            STAGE_A((c + 1) * CHUNK, base + (uint32_t)nxt * 16384u);
            STAGE_B(c + 1, base + 32768u + (uint32_t)nxt * 65536u);
        }

        const int nks = (c == NCH - 1) ? 1 : 4;
        #pragma unroll
        for (int ks = 0; ks < 4; ks++) {
            if (ks >= nks) break;
            const int kcol = ks * 32;
            uint32_t Afrag[4][4];
            #pragma unroll
            for (int mt = 0; mt < 4; mt++) {
                int row = wm * 64 + mt * 16 + arow;
                int colb = kcol + acolsel;
                uint32_t ad = aA + (uint32_t)(row * 128 + (colb ^ ((row & 7) * 16)));
                ldm_x4(Afrag[mt], ad);
            }
            #pragma unroll
            for (int nt = 0; nt < 8; nt++) {
                int rowb = wn * 64 + nt * 8 + brow;
                int colb = kcol + bcolsel;
                uint32_t bd = aB + (uint32_t)(rowb * 128 + (colb ^ ((rowb & 7) * 16)));
                uint32_t Bh[2], Bl[2];
                ldm_x2(Bh, bd);
                ldm_x2(Bl, bd + 32768u);
                #pragma unroll
                for (int mt = 0; mt < 4; mt++) mma_fp16(acc[mt][nt], Afrag[mt], Bh);
                #pragma unroll
                for (int mt = 0; mt < 4; mt++) mma_fp16(acc[mt][nt], Afrag[mt], Bl);
            }
        }
        __syncthreads();
    }

    // epilogue: relu(D + b1) -> 1x1 conv to 2 channels
    #pragma unroll
    for (int mt = 0; mt < 4; mt++) {
        #pragma unroll
        for (int half = 0; half < 2; half++) {
            float s0 = 0.f, s1 = 0.f;
            #pragma unroll
            for (int nt = 0; nt < 8; nt++) {
                int ch0 = wn * 64 + nt * 8 + tq * 2;
                float h0 = fmaxf(acc[mt][nt][half * 2 + 0] + s_b1[ch0], 0.f);
                float h1 = fmaxf(acc[mt][nt][half * 2 + 1] + s_b1[ch0 + 1], 0.f);
                s0 += h0 * s_w2[ch0] + h1 * s_w2[ch0 + 1];
                s1 += h0 * s_w2[CMID + ch0] + h1 * s_w2[CMID + ch0 + 1];
            }
            s0 += __shfl_xor_sync(0xffffffffu, s0, 1);
            s0 += __shfl_xor_sync(0xffffffffu, s0, 2);
            s1 += __shfl_xor_sync(0xffffffffu, s1, 1);
            s1 += __shfl_xor_sync(0xffffffffu, s1, 2);
            if (tq == 0) {
                int px = wm * 64 + mt * 16 + half * 8 + gid;
                atomicAdd(&s_part[px * 2 + 0], s0);
                atomicAdd(&s_part[px * 2 + 1], s1);
            }
        }
    }
    __syncthreads();
    {
        int px = tid >> 1, o = tid & 1;
        outp[((n * 2 + o) * HH + y) * WW + px] = s_part[px * 2 + o] + b2[o];
    }
}

// ---------------- launch ----------------
extern "C" void kernel_launch(void* const* d_in, const int* in_sizes, int n_in,
                              void* d_out, int out_size) {
    const float* contour = (const float*)d_in[0];
    const float* feature = (const float*)d_in[1];
    const int*   batchi  = (const int*)d_in[2];
    const float* w1      = (const float*)d_in[3];
    const float* b1      = (const float*)d_in[4];
    const float* w2      = (const float*)d_in[5];
    const float* b2      = (const float*)d_in[6];
    float* out = (float*)d_out;
    float* out_scat = out + NIMG * 2 * HH * WW;

    static int attr_set = 0;
    if (!attr_set) {
        cudaFuncSetAttribute(k_conv_mma,
                             cudaFuncAttributeMaxDynamicSharedMemorySize,
                             DSMEM_BYTES);
        attr_set = 1;
    }

    k_prep1<<<NV * NC + 1, 128>>>(contour, batchi);
    k_prep2<<<FILL_BLOCKS + FRAME_BLOCKS + WS_BLOCKS, 256>>>(feature, w1);
    k_scatter<<<dim3(HH / 8, NIMG), 128>>>(out_scat);
    k_conv_mma<<<1024, 256, DSMEM_BYTES>>>(b1, w2, b2, out);
}

// round 7
// speedup vs baseline: 4.2462x; 1.2585x over previous
#include <cuda_runtime.h>
#include <cuda_fp16.h>
#include <cstdint>

// ---------------- problem constants ----------------
#define NIMG 8
#define NC   32
#define NV   128
#define HH   128
#define WW   128
#define CIN  64
#define CC   65
#define CMID 256
#define HP   130
#define WP   130
#define KREAL 585          // 65 * 9, k = ci*9 + ky*3 + kx
#define KPAD  640
#define CHUNK 64
#define NCH   10

// ---------------- device scratch ----------------
__device__ float    g_Fx[NC * NV * WW];
__device__ float    g_Fy[NC * NV * HH];
__device__ uint32_t g_Xp2[NIMG * CC * HP * WP];   // fp16 value in low 16 bits
__device__ uint4    g_wBh4[NCH * 2048];           // pre-swizzled fp16 weight planes (32KB/chunk)
__device__ int      g_batch[NC];

// ---------------- helpers ----------------
__device__ __forceinline__ uint32_t smem_u32(const void* p) {
    uint32_t a;
    asm("{ .reg .u64 t; cvta.to.shared.u64 t, %1; cvt.u32.u64 %0, t; }"
        : "=r"(a) : "l"(p));
    return a;
}
#define STS64(a, x, y) \
    asm volatile("st.shared.v2.b32 [%0], {%1, %2};" :: "r"(a), "r"(x), "r"(y) : "memory")
#define STS128(a, v) \
    asm volatile("st.shared.v4.b32 [%0], {%1, %2, %3, %4};" \
                 :: "r"(a), "r"((v).x), "r"((v).y), "r"((v).z), "r"((v).w) : "memory")

__device__ __forceinline__ void ldm_x4(uint32_t* r, uint32_t a) {
    asm volatile("ldmatrix.sync.aligned.m8n8.x4.shared.b16 {%0,%1,%2,%3}, [%4];"
        : "=r"(r[0]), "=r"(r[1]), "=r"(r[2]), "=r"(r[3]) : "r"(a));
}
__device__ __forceinline__ void ldm_x2(uint32_t* r, uint32_t a) {
    asm volatile("ldmatrix.sync.aligned.m8n8.x2.shared.b16 {%0,%1}, [%2];"
        : "=r"(r[0]), "=r"(r[1]) : "r"(a));
}
__device__ __forceinline__ void mma_fp16(float* d, const uint32_t* a, const uint32_t* b) {
    asm volatile("mma.sync.aligned.m16n8k16.row.col.f32.f16.f16.f32 "
        "{%0,%1,%2,%3}, {%4,%5,%6,%7}, {%8,%9}, {%0,%1,%2,%3};"
        : "+f"(d[0]), "+f"(d[1]), "+f"(d[2]), "+f"(d[3])
        : "r"(a[0]), "r"(a[1]), "r"(a[2]), "r"(a[3]), "r"(b[0]), "r"(b[1]));
}

// ---------------- prep kernel 1: tables + batch ----------------
__global__ void k_prep1(const float* __restrict__ contour, const int* bi) {
    int bid = blockIdx.x;
    if (bid < NV * NC) {
        int v = bid & 127, c = bid >> 7, t = threadIdx.x;
        float cx = contour[(c * NV + v) * 2 + 0] * 0.25f;
        float cy = contour[(c * NV + v) * 2 + 1] * 0.25f;
        float dx = (float)t - cx, dy = (float)t - cy;
        const float INV2PI = 0.15915494309189535f;
        g_Fx[(c * NV + v) * WW + t] = INV2PI * __expf(-0.5f * dx * dx);
        g_Fy[(c * NV + v) * HH + t] = __expf(-0.5f * dy * dy);
    } else {
        __shared__ int s_is64;
        if (threadIdx.x == 0) {
            int is64 = 1;
            #pragma unroll
            for (int i = 0; i < 16; i++)
                if (bi[2 * i + 1] != 0) is64 = 0;
            s_is64 = is64;
        }
        __syncthreads();
        int t = threadIdx.x;
        if (t < NC) g_batch[t] = s_is64 ? bi[2 * t] : bi[t];
    }
}

// ---------------- prep kernel 2: fill + frame-zero + weight split ----------------
#define FILL_BLOCKS 2048
#define FRAME_BLOCKS 1049
#define WS_BLOCKS 640
__global__ void k_prep2(const float* __restrict__ feat, const float* __restrict__ w1) {
    int bid = blockIdx.x;
    int tid = threadIdx.x;
    if (bid < FILL_BLOCKS) {
        const int total4 = (NIMG * CIN * HH * WW) / 4;
        for (int i4 = bid * 256 + tid; i4 < total4; i4 += FILL_BLOCKS * 256) {
            int idx = i4 * 4;
            int x = idx & 127;
            int y = (idx >> 7) & 127;
            int ci = (idx >> 14) & 63;
            int n = idx >> 20;
            float4 v = *(const float4*)(feat + idx);
            uint32_t* dst = &g_Xp2[((n * CC + ci + 1) * HP + y + 1) * WP + x + 1];
            dst[0] = (uint32_t)__half_as_ushort(__float2half_rn(v.x));
            dst[1] = (uint32_t)__half_as_ushort(__float2half_rn(v.y));
            dst[2] = (uint32_t)__half_as_ushort(__float2half_rn(v.z));
            dst[3] = (uint32_t)__half_as_ushort(__float2half_rn(v.w));
        }
    } else if (bid < FILL_BLOCKS + FRAME_BLOCKS) {
        const int total = NIMG * CC * 516;
        int idx = (bid - FILL_BLOCKS) * 256 + tid;
        if (idx < total) {
            int plane = idx / 516, e = idx - plane * 516;
            int r, cc;
            if (e < 130)      { r = 0;   cc = e; }
            else if (e < 260) { r = 129; cc = e - 130; }
            else if (e < 388) { r = 1 + (e - 260); cc = 0; }
            else              { r = 1 + (e - 388); cc = 129; }
            g_Xp2[plane * (HP * WP) + r * WP + cc] = 0u;
        }
    } else {
        int idx = (bid - FILL_BLOCKS - FRAME_BLOCKS) * 256 + tid;   // < NCH*16384
        int c = idx >> 14;
        int r = idx & 16383;
        int m = r >> 6, q = r & 63;
        int kg = c * CHUNK + q;
        float v = (kg < KREAL) ? w1[m * KREAL + kg] : 0.f;
        int off = m * 128 + q * 2;
        int sw = off ^ ((off >> 3) & 0x70);
        ((uint16_t*)g_wBh4)[c * 16384 + (sw >> 1)] =
            __half_as_ushort(__float2half_rn(v));
    }
}

// ---------------- scattered = segment_sum of contour maps ----------------
__global__ void k_scatter(float* __restrict__ out_scat) {
    int n = blockIdx.y, y0 = blockIdx.x * 8, x = threadIdx.x;
    __shared__ float s_fy[NV][8];
    float acc[8];
    #pragma unroll
    for (int r = 0; r < 8; r++) acc[r] = 0.f;
    for (int c = 0; c < NC; c++) {
        if (g_batch[c] != n) continue;
        __syncthreads();
        for (int idx = x; idx < NV * 8; idx += 128) {
            int v = idx >> 3, r = idx & 7;
            s_fy[v][r] = g_Fy[(c * NV + v) * HH + (y0 + r)];
        }
        __syncthreads();
        const float* fxp = &g_Fx[(c * NV) * WW + x];
        #pragma unroll 4
        for (int v = 0; v < NV; v++) {
            float fx = fxp[v * WW];
            #pragma unroll
            for (int r = 0; r < 8; r++) acc[r] += fx * s_fy[v][r];
        }
    }
    #pragma unroll
    for (int r = 0; r < 8; r++) {
        out_scat[(n * HH + y0 + r) * WW + x] = acc[r];
        g_Xp2[((n * CC + 0) * HP + (y0 + r + 1)) * WP + (x + 1)] =
            (uint32_t)__half_as_ushort(__float2half_rn(acc[r]));
    }
}

// ---------------- HMMA conv kernel (double-buffered, fp16 1-pass) ----------------
// CTA = one output row (n, y). D[128 px, 256 ch].
// dyn smem: A0 16K | A1 16K | B0 32K | B1 32K = 96KB
#define DSMEM_BYTES (98304 + 1024)

__global__ void __launch_bounds__(256, 1)
k_conv_mma(const float* __restrict__ b1, const float* __restrict__ w2,
           const float* __restrict__ b2, float* __restrict__ outp) {
    extern __shared__ char dsm[];
    __shared__ int   s_off[KPAD];
    __shared__ float s_b1[CMID];
    __shared__ float s_w2[2 * CMID];
    __shared__ float s_part[HH * 2];

    const int tid  = threadIdx.x;
    const int wid  = tid >> 5;
    const int lane = tid & 31;
    const int gid  = lane >> 2;       // 0..7
    const int tq   = lane & 3;        // 0..3
    const int wm   = wid >> 2;        // 0..1 (px half)
    const int wn   = wid & 3;         // 0..3 (ch quarter)
    const int n = blockIdx.x >> 7;
    const int y = blockIdx.x & 127;

    uint32_t sb = smem_u32(dsm);
    const uint32_t base = (sb + 1023u) & ~1023u;
    // A buffers: base + buf*16384 ; B buffers: base + 32768 + buf*32768

    for (int i = tid; i < CMID; i += 256) s_b1[i] = b1[i];
    for (int i = tid; i < 2 * CMID; i += 256) s_w2[i] = w2[i];
    s_part[tid] = 0.f;
    for (int k = tid; k < KPAD; k += 256) {
        int off = -1;
        if (k < KREAL) {
            int ci = k / 9, pos = k - ci * 9;
            int ky = pos / 3, kx = pos - ky * 3;
            off = ci * (HP * WP) + ky * WP + kx;
        }
        s_off[k] = off;
    }

    float acc[4][8][4];
    #pragma unroll
    for (int mt = 0; mt < 4; mt++)
        #pragma unroll
        for (int nt = 0; nt < 8; nt++)
            #pragma unroll
            for (int r = 0; r < 4; r++) acc[mt][nt][r] = 0.f;

    const uint32_t xbase = (uint32_t)n * (CC * HP * WP) + (uint32_t)y * WP;

    const int arow = (lane & 15);
    const int acolsel = (lane >> 4) * 16;
    const int brow = (lane & 7);
    const int bcolsel = ((lane >> 3) & 1) * 16;

    const int sx = tid & 127;          // fixed px per thread for A staging
    const int sg0 = tid >> 7;          // first k-group

#define STAGE_A(k0, aA)                                                        \
    do {                                                                       \
        _Pragma("unroll")                                                      \
        for (int i = 0; i < 8; i++) {                                          \
            int g = sg0 + 2 * i;                                               \
            uint32_t bidx = xbase + (uint32_t)sx;                              \
            int o0 = s_off[(k0) + g * 4 + 0], o1 = s_off[(k0) + g * 4 + 1];    \
            int o2 = s_off[(k0) + g * 4 + 2], o3 = s_off[(k0) + g * 4 + 3];    \
            uint32_t w0 = (o0 >= 0) ? g_Xp2[bidx + o0] : 0u;                   \
            uint32_t w1v = (o1 >= 0) ? g_Xp2[bidx + o1] : 0u;                  \
            uint32_t w2v = (o2 >= 0) ? g_Xp2[bidx + o2] : 0u;                  \
            uint32_t w3v = (o3 >= 0) ? g_Xp2[bidx + o3] : 0u;                  \
            uint32_t h0 = __byte_perm(w0, w1v, 0x5410);                        \
            uint32_t h1 = __byte_perm(w2v, w3v, 0x5410);                       \
            int rb = sx * 128 + g * 8;                                         \
            int sw = rb ^ ((rb >> 3) & 0x70);                                  \
            STS64((aA) + sw, h0, h1);                                          \
        }                                                                      \
    } while (0)

#define STAGE_B(c, aB)                                                         \
    do {                                                                       \
        const uint4* srcH = g_wBh4 + (c) * 2048;                               \
        _Pragma("unroll")                                                      \
        for (int i = 0; i < 8; i++) {                                          \
            int gi = tid + i * 256;                                            \
            uint4 vh = srcH[gi];                                               \
            STS128((aB) + gi * 16, vh);                                        \
        }                                                                      \
    } while (0)

    __syncthreads();
    STAGE_A(0, base);
    STAGE_B(0, base + 32768u);
    __syncthreads();

    for (int c = 0; c < NCH; c++) {
        const int cur = c & 1;
        const uint32_t aA = base + (uint32_t)cur * 16384u;
        const uint32_t aB = base + 32768u + (uint32_t)cur * 32768u;

        if (c < NCH - 1) {
            const int nxt = cur ^ 1;
            STAGE_A((c + 1) * CHUNK, base + (uint32_t)nxt * 16384u);
            STAGE_B(c + 1, base + 32768u + (uint32_t)nxt * 32768u);
        }

        const int nks = (c == NCH - 1) ? 1 : 4;
        #pragma unroll
        for (int ks = 0; ks < 4; ks++) {
            if (ks >= nks) break;
            const int kcol = ks * 32;
            // preload ALL fragments for this k-step (no LDSM->MMA stalls)
            uint32_t Af[4][4];
            #pragma unroll
            for (int mt = 0; mt < 4; mt++) {
                int row = wm * 64 + mt * 16 + arow;
                int colb = kcol + acolsel;
                uint32_t ad = aA + (uint32_t)(row * 128 + (colb ^ ((row & 7) * 16)));
                ldm_x4(Af[mt], ad);
            }
            uint32_t Bf[8][2];
            #pragma unroll
            for (int nt = 0; nt < 8; nt++) {
                int rowb = wn * 64 + nt * 8 + brow;
                int colb = kcol + bcolsel;
                uint32_t bd = aB + (uint32_t)(rowb * 128 + (colb ^ ((rowb & 7) * 16)));
                ldm_x2(Bf[nt], bd);
            }
            // 32 back-to-back HMMA, all-distinct accumulators
            #pragma unroll
            for (int nt = 0; nt < 8; nt++)
                #pragma unroll
                for (int mt = 0; mt < 4; mt++)
                    mma_fp16(acc[mt][nt], Af[mt], Bf[nt]);
        }
        __syncthreads();
    }

    // epilogue: relu(D + b1) -> 1x1 conv to 2 channels
    #pragma unroll
    for (int mt = 0; mt < 4; mt++) {
        #pragma unroll
        for (int half = 0; half < 2; half++) {
            float s0 = 0.f, s1 = 0.f;
            #pragma unroll
            for (int nt = 0; nt < 8; nt++) {
                int ch0 = wn * 64 + nt * 8 + tq * 2;
                float h0 = fmaxf(acc[mt][nt][half * 2 + 0] + s_b1[ch0], 0.f);
                float h1 = fmaxf(acc[mt][nt][half * 2 + 1] + s_b1[ch0 + 1], 0.f);
                s0 += h0 * s_w2[ch0] + h1 * s_w2[ch0 + 1];
                s1 += h0 * s_w2[CMID + ch0] + h1 * s_w2[CMID + ch0 + 1];
            }
            s0 += __shfl_xor_sync(0xffffffffu, s0, 1);
            s0 += __shfl_xor_sync(0xffffffffu, s0, 2);
            s1 += __shfl_xor_sync(0xffffffffu, s1, 1);
            s1 += __shfl_xor_sync(0xffffffffu, s1, 2);
            if (tq == 0) {
                int px = wm * 64 + mt * 16 + half * 8 + gid;
                atomicAdd(&s_part[px * 2 + 0], s0);
                atomicAdd(&s_part[px * 2 + 1], s1);
            }
        }
    }
    __syncthreads();
    {
        int px = tid >> 1, o = tid & 1;
        outp[((n * 2 + o) * HH + y) * WW + px] = s_part[px * 2 + o] + b2[o];
    }
}

// ---------------- launch ----------------
extern "C" void kernel_launch(void* const* d_in, const int* in_sizes, int n_in,
                              void* d_out, int out_size) {
    const float* contour = (const float*)d_in[0];
    const float* feature = (const float*)d_in[1];
    const int*   batchi  = (const int*)d_in[2];
    const float* w1      = (const float*)d_in[3];
    const float* b1      = (const float*)d_in[4];
    const float* w2      = (const float*)d_in[5];
    const float* b2      = (const float*)d_in[6];
    float* out = (float*)d_out;
    float* out_scat = out + NIMG * 2 * HH * WW;

    static int attr_set = 0;
    if (!attr_set) {
        cudaFuncSetAttribute(k_conv_mma,
                             cudaFuncAttributeMaxDynamicSharedMemorySize,
                             DSMEM_BYTES);
        attr_set = 1;
    }

    k_prep1<<<NV * NC + 1, 128>>>(contour, batchi);
    k_prep2<<<FILL_BLOCKS + FRAME_BLOCKS + WS_BLOCKS, 256>>>(feature, w1);
    k_scatter<<<dim3(HH / 8, NIMG), 128>>>(out_scat);
    k_conv_mma<<<1024, 256, DSMEM_BYTES>>>(b1, w2, b2, out);
}

// round 8
// speedup vs baseline: 4.6456x; 1.0941x over previous
#include <cuda_runtime.h>
#include <cuda_fp16.h>
#include <cstdint>

// ---------------- problem constants ----------------
#define NIMG 8
#define NC   32
#define NV   128
#define HH   128
#define WW   128
#define CIN  64
#define CC   65
#define CMID 256
#define HP   130
#define WP   130
#define KREAL 585          // 65 * 9, k = ci*9 + ky*3 + kx
#define KPAD  640
#define CHUNK 64
#define NCH   10

// ---------------- device scratch ----------------
__device__ float    g_Fx[NC * NV * WW];
__device__ float    g_Fy[NC * NV * HH];
__device__ uint32_t g_Xp2[NIMG * CC * HP * WP];   // fp16 value in low 16 bits
__device__ uint4    g_wBh4[NCH * 2048];           // pre-swizzled fp16 weight planes
__device__ int      g_batch[NC];

// ---------------- helpers ----------------
__device__ __forceinline__ uint32_t smem_u32(const void* p) {
    uint32_t a;
    asm("{ .reg .u64 t; cvta.to.shared.u64 t, %1; cvt.u32.u64 %0, t; }"
        : "=r"(a) : "l"(p));
    return a;
}
#define STS64(a, x, y) \
    asm volatile("st.shared.v2.b32 [%0], {%1, %2};" :: "r"(a), "r"(x), "r"(y) : "memory")
#define STS128(a, v) \
    asm volatile("st.shared.v4.b32 [%0], {%1, %2, %3, %4};" \
                 :: "r"(a), "r"((v).x), "r"((v).y), "r"((v).z), "r"((v).w) : "memory")

__device__ __forceinline__ void ldm_x4(uint32_t* r, uint32_t a) {
    asm volatile("ldmatrix.sync.aligned.m8n8.x4.shared.b16 {%0,%1,%2,%3}, [%4];"
        : "=r"(r[0]), "=r"(r[1]), "=r"(r[2]), "=r"(r[3]) : "r"(a));
}
__device__ __forceinline__ void ldm_x2(uint32_t* r, uint32_t a) {
    asm volatile("ldmatrix.sync.aligned.m8n8.x2.shared.b16 {%0,%1}, [%2];"
        : "=r"(r[0]), "=r"(r[1]) : "r"(a));
}
__device__ __forceinline__ void mma_fp16(float* d, const uint32_t* a, const uint32_t* b) {
    asm volatile("mma.sync.aligned.m16n8k16.row.col.f32.f16.f16.f32 "
        "{%0,%1,%2,%3}, {%4,%5,%6,%7}, {%8,%9}, {%0,%1,%2,%3};"
        : "+f"(d[0]), "+f"(d[1]), "+f"(d[2]), "+f"(d[3])
        : "r"(a[0]), "r"(a[1]), "r"(a[2]), "r"(a[3]), "r"(b[0]), "r"(b[1]));
}

// ---------------- prep kernel 1: tables + batch ----------------
__global__ void k_prep1(const float* __restrict__ contour, const int* bi) {
    int bid = blockIdx.x;
    if (bid < NV * NC) {
        int v = bid & 127, c = bid >> 7, t = threadIdx.x;
        float cx = contour[(c * NV + v) * 2 + 0] * 0.25f;
        float cy = contour[(c * NV + v) * 2 + 1] * 0.25f;
        float dx = (float)t - cx, dy = (float)t - cy;
        const float INV2PI = 0.15915494309189535f;
        g_Fx[(c * NV + v) * WW + t] = INV2PI * __expf(-0.5f * dx * dx);
        g_Fy[(c * NV + v) * HH + t] = __expf(-0.5f * dy * dy);
    } else {
        __shared__ int s_is64;
        if (threadIdx.x == 0) {
            int is64 = 1;
            #pragma unroll
            for (int i = 0; i < 16; i++)
                if (bi[2 * i + 1] != 0) is64 = 0;
            s_is64 = is64;
        }
        __syncthreads();
        int t = threadIdx.x;
        if (t < NC) g_batch[t] = s_is64 ? bi[2 * t] : bi[t];
    }
}

// ---------------- prep kernel 2: fill + frame-zero + wsplit + out-init -------
#define FILL_BLOCKS 2048
#define FRAME_BLOCKS 1049
#define WS_BLOCKS 640
#define OINIT_BLOCKS 1024
__global__ void k_prep2(const float* __restrict__ feat, const float* __restrict__ w1,
                        const float* __restrict__ b2, float* __restrict__ outp) {
    int bid = blockIdx.x;
    int tid = threadIdx.x;
    if (bid < FILL_BLOCKS) {
        const int total4 = (NIMG * CIN * HH * WW) / 4;
        for (int i4 = bid * 256 + tid; i4 < total4; i4 += FILL_BLOCKS * 256) {
            int idx = i4 * 4;
            int x = idx & 127;
            int y = (idx >> 7) & 127;
            int ci = (idx >> 14) & 63;
            int n = idx >> 20;
            float4 v = *(const float4*)(feat + idx);
            uint32_t* dst = &g_Xp2[((n * CC + ci + 1) * HP + y + 1) * WP + x + 1];
            dst[0] = (uint32_t)__half_as_ushort(__float2half_rn(v.x));
            dst[1] = (uint32_t)__half_as_ushort(__float2half_rn(v.y));
            dst[2] = (uint32_t)__half_as_ushort(__float2half_rn(v.z));
            dst[3] = (uint32_t)__half_as_ushort(__float2half_rn(v.w));
        }
    } else if (bid < FILL_BLOCKS + FRAME_BLOCKS) {
        const int total = NIMG * CC * 516;
        int idx = (bid - FILL_BLOCKS) * 256 + tid;
        if (idx < total) {
            int plane = idx / 516, e = idx - plane * 516;
            int r, cc;
            if (e < 130)      { r = 0;   cc = e; }
            else if (e < 260) { r = 129; cc = e - 130; }
            else if (e < 388) { r = 1 + (e - 260); cc = 0; }
            else              { r = 1 + (e - 388); cc = 129; }
            g_Xp2[plane * (HP * WP) + r * WP + cc] = 0u;
        }
    } else if (bid < FILL_BLOCKS + FRAME_BLOCKS + WS_BLOCKS) {
        int idx = (bid - FILL_BLOCKS - FRAME_BLOCKS) * 256 + tid;   // < NCH*16384
        int c = idx >> 14;
        int r = idx & 16383;
        int m = r >> 6, q = r & 63;
        int kg = c * CHUNK + q;
        float v = (kg < KREAL) ? w1[m * KREAL + kg] : 0.f;
        int off = m * 128 + q * 2;
        int sw = off ^ ((off >> 3) & 0x70);
        ((uint16_t*)g_wBh4)[c * 16384 + (sw >> 1)] =
            __half_as_ushort(__float2half_rn(v));
    } else {
        // init conv output region with bias b2 (conv CTAs atomicAdd into it)
        int idx = (bid - FILL_BLOCKS - FRAME_BLOCKS - WS_BLOCKS) * 256 + tid;
        int o = (idx >> 14) & 1;
        outp[idx] = b2[o];
    }
}

// ---------------- scattered = segment_sum of contour maps ----------------
__global__ void k_scatter(float* __restrict__ out_scat) {
    int n = blockIdx.y, y0 = blockIdx.x * 8, x = threadIdx.x;
    __shared__ float s_fy[NV][8];
    float acc[8];
    #pragma unroll
    for (int r = 0; r < 8; r++) acc[r] = 0.f;
    for (int c = 0; c < NC; c++) {
        if (g_batch[c] != n) continue;
        __syncthreads();
        for (int idx = x; idx < NV * 8; idx += 128) {
            int v = idx >> 3, r = idx & 7;
            s_fy[v][r] = g_Fy[(c * NV + v) * HH + (y0 + r)];
        }
        __syncthreads();
        const float* fxp = &g_Fx[(c * NV) * WW + x];
        #pragma unroll 4
        for (int v = 0; v < NV; v++) {
            float fx = fxp[v * WW];
            #pragma unroll
            for (int r = 0; r < 8; r++) acc[r] += fx * s_fy[v][r];
        }
    }
    #pragma unroll
    for (int r = 0; r < 8; r++) {
        out_scat[(n * HH + y0 + r) * WW + x] = acc[r];
        g_Xp2[((n * CC + 0) * HP + (y0 + r + 1)) * WP + (x + 1)] =
            (uint32_t)__half_as_ushort(__float2half_rn(acc[r]));
    }
}

// ---------------- HMMA conv kernel: CTA = (row, ch-half) -------------------
// D[128 px, 128 ch] per CTA. 2 CTAs/SM via __launch_bounds__(256, 2).
// dyn smem: A0 16K | A1 16K | B0 16K | B1 16K = 64KB
#define DSMEM_BYTES (65536 + 1024)

__global__ void __launch_bounds__(256, 2)
k_conv_mma(const float* __restrict__ b1, const float* __restrict__ w2,
           float* __restrict__ outp) {
    extern __shared__ char dsm[];
    __shared__ int   s_off[KPAD];
    __shared__ float s_b1[CMID / 2];
    __shared__ float s_w2[2 * CMID / 2];
    __shared__ float s_part[HH * 2];

    const int tid  = threadIdx.x;
    const int wid  = tid >> 5;
    const int lane = tid & 31;
    const int gid  = lane >> 2;       // 0..7
    const int tq   = lane & 3;        // 0..3
    const int wm   = wid >> 2;        // 0..1 (px half: 64 px)
    const int wn   = wid & 3;         // 0..3 (32 ch each)
    const int row  = blockIdx.x >> 1;
    const int ch   = blockIdx.x & 1;  // channel half
    const int n = row >> 7;
    const int y = row & 127;
    const int chbase = ch * 128;

    uint32_t sb = smem_u32(dsm);
    const uint32_t base = (sb + 1023u) & ~1023u;
    // A buffers: base + buf*16384 ; B buffers: base + 32768 + buf*16384

    for (int i = tid; i < 128; i += 256) {
        s_b1[i] = b1[chbase + i];
        s_w2[i] = w2[chbase + i];
        s_w2[128 + i] = w2[CMID + chbase + i];
    }
    s_part[tid] = 0.f;
    for (int k = tid; k < KPAD; k += 256) {
        int off = -1;
        if (k < KREAL) {
            int ci = k / 9, pos = k - ci * 9;
            int ky = pos / 3, kx = pos - ky * 3;
            off = ci * (HP * WP) + ky * WP + kx;
        }
        s_off[k] = off;
    }

    float acc[4][4][4];
    #pragma unroll
    for (int mt = 0; mt < 4; mt++)
        #pragma unroll
        for (int nt = 0; nt < 4; nt++)
            #pragma unroll
            for (int r = 0; r < 4; r++) acc[mt][nt][r] = 0.f;

    const uint32_t xbase = (uint32_t)n * (CC * HP * WP) + (uint32_t)y * WP;

    const int arow = (lane & 15);
    const int acolsel = (lane >> 4) * 16;
    const int brow = (lane & 7);
    const int bcolsel = ((lane >> 3) & 1) * 16;

    const int sx = tid & 127;          // fixed px for A staging
    const int sg0 = tid >> 7;          // first k-group

#define STAGE_A(k0, aA)                                                        \
    do {                                                                       \
        _Pragma("unroll")                                                      \
        for (int i = 0; i < 8; i++) {                                          \
            int g = sg0 + 2 * i;                                               \
            uint32_t bidx = xbase + (uint32_t)sx;                              \
            int o0 = s_off[(k0) + g * 4 + 0], o1 = s_off[(k0) + g * 4 + 1];    \
            int o2 = s_off[(k0) + g * 4 + 2], o3 = s_off[(k0) + g * 4 + 3];    \
            uint32_t w0 = (o0 >= 0) ? g_Xp2[bidx + o0] : 0u;                   \
            uint32_t w1v = (o1 >= 0) ? g_Xp2[bidx + o1] : 0u;                  \
            uint32_t w2v = (o2 >= 0) ? g_Xp2[bidx + o2] : 0u;                  \
            uint32_t w3v = (o3 >= 0) ? g_Xp2[bidx + o3] : 0u;                  \
            uint32_t h0 = __byte_perm(w0, w1v, 0x5410);                        \
            uint32_t h1 = __byte_perm(w2v, w3v, 0x5410);                       \
            int rb = sx * 128 + g * 8;                                         \
            int sw = rb ^ ((rb >> 3) & 0x70);                                  \
            STS64((aA) + sw, h0, h1);                                          \
        }                                                                      \
    } while (0)

#define STAGE_B(c, aB)                                                         \
    do {                                                                       \
        const uint4* src = g_wBh4 + (c) * 2048 + ch * 1024;                    \
        _Pragma("unroll")                                                      \
        for (int i = 0; i < 4; i++) {                                          \
            int gi = tid + i * 256;                                            \
            uint4 vh = src[gi];                                                \
            STS128((aB) + gi * 16, vh);                                        \
        }                                                                      \
    } while (0)

    __syncthreads();
    STAGE_A(0, base);
    STAGE_B(0, base + 32768u);
    __syncthreads();

    for (int c = 0; c < NCH; c++) {
        const int cur = c & 1;
        const uint32_t aA = base + (uint32_t)cur * 16384u;
        const uint32_t aB = base + 32768u + (uint32_t)cur * 16384u;

        if (c < NCH - 1) {
            const int nxt = cur ^ 1;
            STAGE_A((c + 1) * CHUNK, base + (uint32_t)nxt * 16384u);
            STAGE_B(c + 1, base + 32768u + (uint32_t)nxt * 16384u);
        }

        const int nks = (c == NCH - 1) ? 1 : 4;
        #pragma unroll
        for (int ks = 0; ks < 4; ks++) {
            if (ks >= nks) break;
            const int kcol = ks * 32;
            uint32_t Af[4][4];
            #pragma unroll
            for (int mt = 0; mt < 4; mt++) {
                int r0 = wm * 64 + mt * 16 + arow;
                int colb = kcol + acolsel;
                uint32_t ad = aA + (uint32_t)(r0 * 128 + (colb ^ ((r0 & 7) * 16)));
                ldm_x4(Af[mt], ad);
            }
            uint32_t Bf[4][2];
            #pragma unroll
            for (int nt = 0; nt < 4; nt++) {
                int rowb = wn * 32 + nt * 8 + brow;
                int colb = kcol + bcolsel;
                uint32_t bd = aB + (uint32_t)(rowb * 128 + (colb ^ ((rowb & 7) * 16)));
                ldm_x2(Bf[nt], bd);
            }
            #pragma unroll
            for (int nt = 0; nt < 4; nt++)
                #pragma unroll
                for (int mt = 0; mt < 4; mt++)
                    mma_fp16(acc[mt][nt], Af[mt], Bf[nt]);
        }
        __syncthreads();
    }

    // epilogue: relu(D + b1) -> partial 1x1 conv, reduce in smem, atomicAdd gmem
    #pragma unroll
    for (int mt = 0; mt < 4; mt++) {
        #pragma unroll
        for (int half = 0; half < 2; half++) {
            float s0 = 0.f, s1 = 0.f;
            #pragma unroll
            for (int nt = 0; nt < 4; nt++) {
                int cl = wn * 32 + nt * 8 + tq * 2;       // local ch 0..127
                float h0 = fmaxf(acc[mt][nt][half * 2 + 0] + s_b1[cl], 0.f);
                float h1 = fmaxf(acc[mt][nt][half * 2 + 1] + s_b1[cl + 1], 0.f);
                s0 += h0 * s_w2[cl] + h1 * s_w2[cl + 1];
                s1 += h0 * s_w2[128 + cl] + h1 * s_w2[128 + cl + 1];
            }
            s0 += __shfl_xor_sync(0xffffffffu, s0, 1);
            s0 += __shfl_xor_sync(0xffffffffu, s0, 2);
            s1 += __shfl_xor_sync(0xffffffffu, s1, 1);
            s1 += __shfl_xor_sync(0xffffffffu, s1, 2);
            if (tq == 0) {
                int px = wm * 64 + mt * 16 + half * 8 + gid;
                atomicAdd(&s_part[px * 2 + 0], s0);
                atomicAdd(&s_part[px * 2 + 1], s1);
            }
        }
    }
    __syncthreads();
    {
        int px = tid >> 1, o = tid & 1;
        atomicAdd(&outp[((n * 2 + o) * HH + y) * WW + px], s_part[px * 2 + o]);
    }
}

// ---------------- launch ----------------
extern "C" void kernel_launch(void* const* d_in, const int* in_sizes, int n_in,
                              void* d_out, int out_size) {
    const float* contour = (const float*)d_in[0];
    const float* feature = (const float*)d_in[1];
    const int*   batchi  = (const int*)d_in[2];
    const float* w1      = (const float*)d_in[3];
    const float* b1      = (const float*)d_in[4];
    const float* w2      = (const float*)d_in[5];
    const float* b2      = (const float*)d_in[6];
    float* out = (float*)d_out;
    float* out_scat = out + NIMG * 2 * HH * WW;

    static int attr_set = 0;
    if (!attr_set) {
        cudaFuncSetAttribute(k_conv_mma,
                             cudaFuncAttributeMaxDynamicSharedMemorySize,
                             DSMEM_BYTES);
        attr_set = 1;
    }

    k_prep1<<<NV * NC + 1, 128>>>(contour, batchi);
    k_prep2<<<FILL_BLOCKS + FRAME_BLOCKS + WS_BLOCKS + OINIT_BLOCKS, 256>>>(
        feature, w1, b2, out);
    k_scatter<<<dim3(HH / 8, NIMG), 128>>>(out_scat);
    k_conv_mma<<<2048, 256, DSMEM_BYTES>>>(b1, w2, out);
}

// round 9
// speedup vs baseline: 4.6863x; 1.0087x over previous
#include <cuda_runtime.h>
#include <cuda_fp16.h>
#include <cstdint>

// ---------------- problem constants ----------------
#define NIMG 8
#define NC   32
#define NV   128
#define HH   128
#define WW   128
#define CIN  64
#define CC   65
#define CMID 256
#define HP   130
#define WP   130
#define KREAL 585          // 65 * 9, k = ci*9 + ky*3 + kx
#define KPAD  640
#define CHUNK 64
#define NCH   10

// ---------------- device scratch ----------------
__device__ float    g_Fx[NC * NV * WW];
__device__ float    g_Fy[NC * NV * HH];
__device__ uint32_t g_Xp2[NIMG * CC * HP * WP];   // fp16 value in low 16 bits
__device__ uint4    g_wBh4[NCH * 2048];           // pre-swizzled fp16 weight planes
__device__ int      g_batch[NC];

// ---------------- helpers ----------------
__device__ __forceinline__ uint32_t smem_u32(const void* p) {
    uint32_t a;
    asm("{ .reg .u64 t; cvta.to.shared.u64 t, %1; cvt.u32.u64 %0, t; }"
        : "=r"(a) : "l"(p));
    return a;
}
__device__ __forceinline__ void ldm_x4(uint32_t* r, uint32_t a) {
    asm volatile("ldmatrix.sync.aligned.m8n8.x4.shared.b16 {%0,%1,%2,%3}, [%4];"
        : "=r"(r[0]), "=r"(r[1]), "=r"(r[2]), "=r"(r[3]) : "r"(a));
}
__device__ __forceinline__ void ldm_x2(uint32_t* r, uint32_t a) {
    asm volatile("ldmatrix.sync.aligned.m8n8.x2.shared.b16 {%0,%1}, [%2];"
        : "=r"(r[0]), "=r"(r[1]) : "r"(a));
}
__device__ __forceinline__ void mma_fp16(float* d, const uint32_t* a, const uint32_t* b) {
    asm volatile("mma.sync.aligned.m16n8k16.row.col.f32.f16.f16.f32 "
        "{%0,%1,%2,%3}, {%4,%5,%6,%7}, {%8,%9}, {%0,%1,%2,%3};"
        : "+f"(d[0]), "+f"(d[1]), "+f"(d[2]), "+f"(d[3])
        : "r"(a[0]), "r"(a[1]), "r"(a[2]), "r"(a[3]), "r"(b[0]), "r"(b[1]));
}
#define CP_ASYNC16(dst, src) \
    asm volatile("cp.async.cg.shared.global [%0], [%1], 16;" \
                 :: "r"(dst), "l"(src) : "memory")
#define CP_COMMIT()  asm volatile("cp.async.commit_group;" ::: "memory")
#define CP_WAIT0()   asm volatile("cp.async.wait_group 0;" ::: "memory")

// ---------------- prep kernel 1: tables + batch ----------------
__global__ void k_prep1(const float* __restrict__ contour, const int* bi) {
    int bid = blockIdx.x;
    if (bid < NV * NC) {
        int v = bid & 127, c = bid >> 7, t = threadIdx.x;
        float cx = contour[(c * NV + v) * 2 + 0] * 0.25f;
        float cy = contour[(c * NV + v) * 2 + 1] * 0.25f;
        float dx = (float)t - cx, dy = (float)t - cy;
        const float INV2PI = 0.15915494309189535f;
        g_Fx[(c * NV + v) * WW + t] = INV2PI * __expf(-0.5f * dx * dx);
        g_Fy[(c * NV + v) * HH + t] = __expf(-0.5f * dy * dy);
    } else {
        __shared__ int s_is64;
        if (threadIdx.x == 0) {
            int is64 = 1;
            #pragma unroll
            for (int i = 0; i < 16; i++)
                if (bi[2 * i + 1] != 0) is64 = 0;
            s_is64 = is64;
        }
        __syncthreads();
        int t = threadIdx.x;
        if (t < NC) g_batch[t] = s_is64 ? bi[2 * t] : bi[t];
    }
}

// ---------------- prep kernel 2: fill + frame-zero + wsplit + out-init -------
#define FILL_BLOCKS 2048
#define FRAME_BLOCKS 1049
#define WS_BLOCKS 640
#define OINIT_BLOCKS 1024
__global__ void k_prep2(const float* __restrict__ feat, const float* __restrict__ w1,
                        const float* __restrict__ b2, float* __restrict__ outp) {
    int bid = blockIdx.x;
    int tid = threadIdx.x;
    if (bid < FILL_BLOCKS) {
        const int total4 = (NIMG * CIN * HH * WW) / 4;
        for (int i4 = bid * 256 + tid; i4 < total4; i4 += FILL_BLOCKS * 256) {
            int idx = i4 * 4;
            int x = idx & 127;
            int y = (idx >> 7) & 127;
            int ci = (idx >> 14) & 63;
            int n = idx >> 20;
            float4 v = *(const float4*)(feat + idx);
            uint32_t* dst = &g_Xp2[((n * CC + ci + 1) * HP + y + 1) * WP + x + 1];
            dst[0] = (uint32_t)__half_as_ushort(__float2half_rn(v.x));
            dst[1] = (uint32_t)__half_as_ushort(__float2half_rn(v.y));
            dst[2] = (uint32_t)__half_as_ushort(__float2half_rn(v.z));
            dst[3] = (uint32_t)__half_as_ushort(__float2half_rn(v.w));
        }
    } else if (bid < FILL_BLOCKS + FRAME_BLOCKS) {
        const int total = NIMG * CC * 516;
        int idx = (bid - FILL_BLOCKS) * 256 + tid;
        if (idx < total) {
            int plane = idx / 516, e = idx - plane * 516;
            int r, cc;
            if (e < 130)      { r = 0;   cc = e; }
            else if (e < 260) { r = 129; cc = e - 130; }
            else if (e < 388) { r = 1 + (e - 260); cc = 0; }
            else              { r = 1 + (e - 388); cc = 129; }
            g_Xp2[plane * (HP * WP) + r * WP + cc] = 0u;
        }
    } else if (bid < FILL_BLOCKS + FRAME_BLOCKS + WS_BLOCKS) {
        int idx = (bid - FILL_BLOCKS - FRAME_BLOCKS) * 256 + tid;   // < NCH*16384
        int c = idx >> 14;
        int r = idx & 16383;
        int m = r >> 6, q = r & 63;
        int kg = c * CHUNK + q;
        float v = (kg < KREAL) ? w1[m * KREAL + kg] : 0.f;
        int off = m * 128 + q * 2;
        int sw = off ^ ((off >> 3) & 0x70);
        ((uint16_t*)g_wBh4)[c * 16384 + (sw >> 1)] =
            __half_as_ushort(__float2half_rn(v));
    } else {
        int idx = (bid - FILL_BLOCKS - FRAME_BLOCKS - WS_BLOCKS) * 256 + tid;
        int o = (idx >> 14) & 1;
        outp[idx] = b2[o];
    }
}

// ---------------- scattered = segment_sum of contour maps ----------------
__global__ void k_scatter(float* __restrict__ out_scat) {
    int n = blockIdx.y, y0 = blockIdx.x * 8, x = threadIdx.x;
    __shared__ float s_fy[NV][8];
    float acc[8];
    #pragma unroll
    for (int r = 0; r < 8; r++) acc[r] = 0.f;
    for (int c = 0; c < NC; c++) {
        if (g_batch[c] != n) continue;
        __syncthreads();
        for (int idx = x; idx < NV * 8; idx += 128) {
            int v = idx >> 3, r = idx & 7;
            s_fy[v][r] = g_Fy[(c * NV + v) * HH + (y0 + r)];
        }
        __syncthreads();
        const float* fxp = &g_Fx[(c * NV) * WW + x];
        #pragma unroll 4
        for (int v = 0; v < NV; v++) {
            float fx = fxp[v * WW];
            #pragma unroll
            for (int r = 0; r < 8; r++) acc[r] += fx * s_fy[v][r];
        }
    }
    #pragma unroll
    for (int r = 0; r < 8; r++) {
        out_scat[(n * HH + y0 + r) * WW + x] = acc[r];
        g_Xp2[((n * CC + 0) * HP + (y0 + r + 1)) * WP + (x + 1)] =
            (uint32_t)__half_as_ushort(__float2half_rn(acc[r]));
    }
}

// ---------------- HMMA conv kernel: CTA = (row, ch-half) -------------------
// D[128 px, 128 ch] per CTA. 2 CTAs/SM via __launch_bounds__(256, 2).
// dyn smem: A0 16K | A1 16K | B0 16K | B1 16K = 64KB
#define DSMEM_BYTES (65536 + 1024)

__global__ void __launch_bounds__(256, 2)
k_conv_mma(const float* __restrict__ b1, const float* __restrict__ w2,
           float* __restrict__ outp) {
    extern __shared__ char dsm[];
    __shared__ int   s_off[KPAD];
    __shared__ float s_b1[CMID / 2];
    __shared__ float s_w2[2 * CMID / 2];
    __shared__ float s_part[HH * 2];

    const int tid  = threadIdx.x;
    const int wid  = tid >> 5;
    const int lane = tid & 31;
    const int gid  = lane >> 2;       // 0..7
    const int tq   = lane & 3;        // 0..3
    const int wm   = wid >> 2;        // 0..1 (px half: 64 px)
    const int wn   = wid & 3;         // 0..3 (32 ch each)
    const int row  = blockIdx.x >> 1;
    const int ch   = blockIdx.x & 1;  // channel half
    const int n = row >> 7;
    const int y = row & 127;
    const int chbase = ch * 128;

    const uint32_t sbu = smem_u32(dsm);
    const uint32_t pad = (1024u - (sbu & 1023u)) & 1023u;
    const uint32_t base = sbu + pad;          // u32 smem address, 1KB aligned
    char* const sp = dsm + pad;               // same, as generic pointer
    // A buffers: +buf*16384 ; B buffers: +32768 + buf*16384

    for (int i = tid; i < 128; i += 256) {
        s_b1[i] = b1[chbase + i];
        s_w2[i] = w2[chbase + i];
        s_w2[128 + i] = w2[CMID + chbase + i];
    }
    s_part[tid] = 0.f;
    for (int k = tid; k < KPAD; k += 256) {
        int off = -1;
        if (k < KREAL) {
            int ci = k / 9, pos = k - ci * 9;
            int ky = pos / 3, kx = pos - ky * 3;
            off = ci * (HP * WP) + ky * WP + kx;
        }
        s_off[k] = off;
    }

    float acc[4][4][4];
    #pragma unroll
    for (int mt = 0; mt < 4; mt++)
        #pragma unroll
        for (int nt = 0; nt < 4; nt++)
            #pragma unroll
            for (int r = 0; r < 4; r++) acc[mt][nt][r] = 0.f;

    const uint32_t xbase = (uint32_t)n * (CC * HP * WP) + (uint32_t)y * WP;

    const int arow = (lane & 15);
    const int acolsel = (lane >> 4) * 16;
    const int brow = (lane & 7);
    const int bcolsel = ((lane >> 3) & 1) * 16;

    const int sx = tid & 127;          // fixed px for A staging
    const int sg0 = tid >> 7;          // first k-group

    // A staging: plain C loads/stores so ptxas can schedule around MMA
#define STAGE_A(k0, bufoff)                                                    \
    do {                                                                       \
        _Pragma("unroll")                                                      \
        for (int i = 0; i < 8; i++) {                                          \
            int g = sg0 + 2 * i;                                               \
            uint32_t bidx = xbase + (uint32_t)sx;                              \
            int o0 = s_off[(k0) + g * 4 + 0], o1 = s_off[(k0) + g * 4 + 1];    \
            int o2 = s_off[(k0) + g * 4 + 2], o3 = s_off[(k0) + g * 4 + 3];    \
            uint32_t w0 = (o0 >= 0) ? g_Xp2[bidx + o0] : 0u;                   \
            uint32_t w1v = (o1 >= 0) ? g_Xp2[bidx + o1] : 0u;                  \
            uint32_t w2v = (o2 >= 0) ? g_Xp2[bidx + o2] : 0u;                  \
            uint32_t w3v = (o3 >= 0) ? g_Xp2[bidx + o3] : 0u;                  \
            uint32_t h0 = __byte_perm(w0, w1v, 0x5410);                        \
            uint32_t h1 = __byte_perm(w2v, w3v, 0x5410);                       \
            int rb = sx * 128 + g * 8;                                         \
            int sw = rb ^ ((rb >> 3) & 0x70);                                  \
            *(uint2*)(sp + (bufoff) + sw) = make_uint2(h0, h1);                \
        }                                                                      \
    } while (0)

    // B staging: async 16B copies (weights pre-swizzled -> identity copy)
#define STAGE_B(c, aB)                                                         \
    do {                                                                       \
        const char* src = (const char*)(g_wBh4 + (c) * 2048 + ch * 1024);      \
        _Pragma("unroll")                                                      \
        for (int i = 0; i < 4; i++) {                                          \
            int gi = tid + i * 256;                                            \
            CP_ASYNC16((aB) + gi * 16, src + gi * 16);                         \
        }                                                                      \
        CP_COMMIT();                                                           \
    } while (0)

    __syncthreads();
    STAGE_A(0, 0u);
    STAGE_B(0, base + 32768u);
    CP_WAIT0();
    __syncthreads();

    for (int c = 0; c < NCH; c++) {
        const int cur = c & 1;
        const uint32_t aA = base + (uint32_t)cur * 16384u;
        const uint32_t aB = base + 32768u + (uint32_t)cur * 16384u;

        if (c < NCH - 1) {
            const int nxt = cur ^ 1;
            STAGE_A((c + 1) * CHUNK, (uint32_t)nxt * 16384u);
            STAGE_B(c + 1, base + 32768u + (uint32_t)nxt * 16384u);
        }

        const int nks = (c == NCH - 1) ? 1 : 4;
        #pragma unroll
        for (int ks = 0; ks < 4; ks++) {
            if (ks >= nks) break;
            const int kcol = ks * 32;
            uint32_t Af[4][4];
            #pragma unroll
            for (int mt = 0; mt < 4; mt++) {
                int r0 = wm * 64 + mt * 16 + arow;
                int colb = kcol + acolsel;
                uint32_t ad = aA + (uint32_t)(r0 * 128 + (colb ^ ((r0 & 7) * 16)));
                ldm_x4(Af[mt], ad);
            }
            uint32_t Bf[4][2];
            #pragma unroll
            for (int nt = 0; nt < 4; nt++) {
                int rowb = wn * 32 + nt * 8 + brow;
                int colb = kcol + bcolsel;
                uint32_t bd = aB + (uint32_t)(rowb * 128 + (colb ^ ((rowb & 7) * 16)));
                ldm_x2(Bf[nt], bd);
            }
            #pragma unroll
            for (int nt = 0; nt < 4; nt++)
                #pragma unroll
                for (int mt = 0; mt < 4; mt++)
                    mma_fp16(acc[mt][nt], Af[mt], Bf[nt]);
        }
        CP_WAIT0();        // next-chunk B copies landed (hidden behind MMAs)
        __syncthreads();   // next-chunk A stores visible to all warps
    }

    // epilogue: relu(D + b1) -> partial 1x1 conv, reduce in smem, atomicAdd gmem
    #pragma unroll
    for (int mt = 0; mt < 4; mt++) {
        #pragma unroll
        for (int half = 0; half < 2; half++) {
            float s0 = 0.f, s1 = 0.f;
            #pragma unroll
            for (int nt = 0; nt < 4; nt++) {
                int cl = wn * 32 + nt * 8 + tq * 2;       // local ch 0..127
                float h0 = fmaxf(acc[mt][nt][half * 2 + 0] + s_b1[cl], 0.f);
                float h1 = fmaxf(acc[mt][nt][half * 2 + 1] + s_b1[cl + 1], 0.f);
                s0 += h0 * s_w2[cl] + h1 * s_w2[cl + 1];
                s1 += h0 * s_w2[128 + cl] + h1 * s_w2[128 + cl + 1];
            }
            s0 += __shfl_xor_sync(0xffffffffu, s0, 1);
            s0 += __shfl_xor_sync(0xffffffffu, s0, 2);
            s1 += __shfl_xor_sync(0xffffffffu, s1, 1);
            s1 += __shfl_xor_sync(0xffffffffu, s1, 2);
            if (tq == 0) {
                int px = wm * 64 + mt * 16 + half * 8 + gid;
                atomicAdd(&s_part[px * 2 + 0], s0);
                atomicAdd(&s_part[px * 2 + 1], s1);
            }
        }
    }
    __syncthreads();
    {
        int px = tid >> 1, o = tid & 1;
        atomicAdd(&outp[((n * 2 + o) * HH + y) * WW + px], s_part[px * 2 + o]);
    }
}

// ---------------- launch ----------------
extern "C" void kernel_launch(void* const* d_in, const int* in_sizes, int n_in,
                              void* d_out, int out_size) {
    const float* contour = (const float*)d_in[0];
    const float* feature = (const float*)d_in[1];
    const int*   batchi  = (const int*)d_in[2];
    const float* w1      = (const float*)d_in[3];
    const float* b1      = (const float*)d_in[4];
    const float* w2      = (const float*)d_in[5];
    const float* b2      = (const float*)d_in[6];
    float* out = (float*)d_out;
    float* out_scat = out + NIMG * 2 * HH * WW;

    static int attr_set = 0;
    if (!attr_set) {
        cudaFuncSetAttribute(k_conv_mma,
                             cudaFuncAttributeMaxDynamicSharedMemorySize,
                             DSMEM_BYTES);
        attr_set = 1;
    }

    k_prep1<<<NV * NC + 1, 128>>>(contour, batchi);
    k_prep2<<<FILL_BLOCKS + FRAME_BLOCKS + WS_BLOCKS + OINIT_BLOCKS, 256>>>(
        feature, w1, b2, out);
    k_scatter<<<dim3(HH / 8, NIMG), 128>>>(out_scat);
    k_conv_mma<<<2048, 256, DSMEM_BYTES>>>(b1, w2, out);
}

// round 10
// speedup vs baseline: 6.2525x; 1.3342x over previous
#include <cuda_runtime.h>
#include <cuda_fp16.h>
#include <cstdint>

// ---------------- problem constants ----------------
#define NIMG 8
#define NC   32
#define NV   128
#define HH   128
#define WW   128
#define CIN  64
#define CC   65
#define CMID 256
#define HP   130
#define KREAL 585          // 65 * 9, k = ci*9 + ky*3 + kx
#define KPAD  640
#define CHUNK 64
#define NCH   10

// shifted-input buffer strides (fp16 elements)
#define CS  (HP * 128)           // per channel  = 16640
#define NS  (CC * CS)            // per image    = 1081600
#define KXS (NIMG * NS)          // per kx shift = 8652800

// ---------------- device scratch ----------------
__device__ float    g_Fx[NC * NV * WW];
__device__ float    g_Fy[NC * NV * HH];
__device__ uint16_t g_Xs[3 * KXS];       // 3 kx-shifted fp16 padded inputs (52MB)
__device__ uint4    g_wBh4[NCH * 2048];  // pre-swizzled fp16 weight planes
__device__ int      g_batch[NC];

// ---------------- helpers ----------------
__device__ __forceinline__ uint32_t smem_u32(const void* p) {
    uint32_t a;
    asm("{ .reg .u64 t; cvta.to.shared.u64 t, %1; cvt.u32.u64 %0, t; }"
        : "=r"(a) : "l"(p));
    return a;
}
__device__ __forceinline__ void ldm_x4_trans(uint32_t* r, uint32_t a) {
    asm volatile("ldmatrix.sync.aligned.m8n8.x4.trans.shared.b16 {%0,%1,%2,%3}, [%4];"
        : "=r"(r[0]), "=r"(r[1]), "=r"(r[2]), "=r"(r[3]) : "r"(a));
}
__device__ __forceinline__ void ldm_x2(uint32_t* r, uint32_t a) {
    asm volatile("ldmatrix.sync.aligned.m8n8.x2.shared.b16 {%0,%1}, [%2];"
        : "=r"(r[0]), "=r"(r[1]) : "r"(a));
}
__device__ __forceinline__ void mma_fp16(float* d, const uint32_t* a, const uint32_t* b) {
    asm volatile("mma.sync.aligned.m16n8k16.row.col.f32.f16.f16.f32 "
        "{%0,%1,%2,%3}, {%4,%5,%6,%7}, {%8,%9}, {%0,%1,%2,%3};"
        : "+f"(d[0]), "+f"(d[1]), "+f"(d[2]), "+f"(d[3])
        : "r"(a[0]), "r"(a[1]), "r"(a[2]), "r"(a[3]), "r"(b[0]), "r"(b[1]));
}
#define CP_ASYNC16(dst, src) \
    asm volatile("cp.async.cg.shared.global [%0], [%1], 16;" \
                 :: "r"(dst), "l"(src) : "memory")
#define CP_ASYNC16Z(dst, src, sz) \
    asm volatile("cp.async.cg.shared.global [%0], [%1], 16, %2;" \
                 :: "r"(dst), "l"(src), "r"(sz) : "memory")
#define CP_COMMIT()  asm volatile("cp.async.commit_group;" ::: "memory")
#define CP_WAIT0()   asm volatile("cp.async.wait_group 0;" ::: "memory")

// ---------------- prep kernel 1: tables + batch ----------------
__global__ void k_prep1(const float* __restrict__ contour, const int* bi) {
    int bid = blockIdx.x;
    if (bid < NV * NC) {
        int v = bid & 127, c = bid >> 7, t = threadIdx.x;
        float cx = contour[(c * NV + v) * 2 + 0] * 0.25f;
        float cy = contour[(c * NV + v) * 2 + 1] * 0.25f;
        float dx = (float)t - cx, dy = (float)t - cy;
        const float INV2PI = 0.15915494309189535f;
        g_Fx[(c * NV + v) * WW + t] = INV2PI * __expf(-0.5f * dx * dx);
        g_Fy[(c * NV + v) * HH + t] = __expf(-0.5f * dy * dy);
    } else {
        __shared__ int s_is64;
        if (threadIdx.x == 0) {
            int is64 = 1;
            #pragma unroll
            for (int i = 0; i < 16; i++)
                if (bi[2 * i + 1] != 0) is64 = 0;
            s_is64 = is64;
        }
        __syncthreads();
        int t = threadIdx.x;
        if (t < NC) g_batch[t] = s_is64 ? bi[2 * t] : bi[t];
    }
}

// ---------------- prep kernel 2: fill(x3) + zero + wsplit + out-init --------
#define FILL_BLOCKS 2048
#define ZERO_BLOCKS 2089         // (399360 + 2*67600 + 255)/256
#define WS_BLOCKS 640
#define OINIT_BLOCKS 1024
__global__ void k_prep2(const float* __restrict__ feat, const float* __restrict__ w1,
                        const float* __restrict__ b2, float* __restrict__ outp) {
    int bid = blockIdx.x;
    int tid = threadIdx.x;
    if (bid < FILL_BLOCKS) {
        // feature -> 3 kx-shifted fp16 buffers (channels 1..64)
        const int total = NIMG * CIN * HH * WW;
        for (int idx = bid * 256 + tid; idx < total; idx += FILL_BLOCKS * 256) {
            int x = idx & 127;
            int y = (idx >> 7) & 127;
            int ci = (idx >> 14) & 63;
            int n = idx >> 20;
            uint16_t v = __half_as_ushort(__float2half_rn(feat[idx]));
            int base = n * NS + (ci + 1) * CS + (y + 1) * 128;
            #pragma unroll
            for (int kx = 0; kx < 3; kx++) {
                int xq = x + 1 - kx;
                if (xq >= 0 && xq < 128) g_Xs[kx * KXS + base + xq] = v;
            }
        }
    } else if (bid < FILL_BLOCKS + ZERO_BLOCKS) {
        int idx = (bid - FILL_BLOCKS) * 256 + tid;
        if (idx < 399360) {
            // top/bottom pad rows of every (kx, n, c) plane
            int x = idx & 127;
            int rr = idx >> 7;                 // 0..3119
            int yy = (rr & 1) ? 129 : 0;
            int kxnc = rr >> 1;                // 0..1559
            int c = kxnc % 65;
            int nn = (kxnc / 65) & 7;
            int kx = kxnc / (65 * 8);
            g_Xs[kx * KXS + nn * NS + c * CS + yy * 128 + x] = 0;
        } else if (idx < 399360 + 2 * 67600) {
            // left edge of buf kx=0 (x=0) and right edge of buf kx=2 (x=127)
            int j = idx - 399360;
            int set = j / 67600;
            int jj = j % 67600;
            int yy = jj % 130;
            int c = (jj / 130) % 65;
            int nn = jj / (130 * 65);
            int kx = set ? 2 : 0;
            int x = set ? 127 : 0;
            g_Xs[kx * KXS + nn * NS + c * CS + yy * 128 + x] = 0;
        }
    } else if (bid < FILL_BLOCKS + ZERO_BLOCKS + WS_BLOCKS) {
        int idx = (bid - FILL_BLOCKS - ZERO_BLOCKS) * 256 + tid;   // < NCH*16384
        int c = idx >> 14;
        int r = idx & 16383;
        int m = r >> 6, q = r & 63;
        int kg = c * CHUNK + q;
        float v = (kg < KREAL) ? w1[m * KREAL + kg] : 0.f;
        int off = m * 128 + q * 2;
        int sw = off ^ ((off >> 3) & 0x70);
        ((uint16_t*)g_wBh4)[c * 16384 + (sw >> 1)] =
            __half_as_ushort(__float2half_rn(v));
    } else {
        int idx = (bid - FILL_BLOCKS - ZERO_BLOCKS - WS_BLOCKS) * 256 + tid;
        int o = (idx >> 14) & 1;
        outp[idx] = b2[o];
    }
}

// ---------------- scattered = segment_sum of contour maps ----------------
__global__ void k_scatter(float* __restrict__ out_scat) {
    int n = blockIdx.y, y0 = blockIdx.x * 8, x = threadIdx.x;
    __shared__ float s_fy[NV][8];
    float acc[8];
    #pragma unroll
    for (int r = 0; r < 8; r++) acc[r] = 0.f;
    for (int c = 0; c < NC; c++) {
        if (g_batch[c] != n) continue;
        __syncthreads();
        for (int idx = x; idx < NV * 8; idx += 128) {
            int v = idx >> 3, r = idx & 7;
            s_fy[v][r] = g_Fy[(c * NV + v) * HH + (y0 + r)];
        }
        __syncthreads();
        const float* fxp = &g_Fx[(c * NV) * WW + x];
        #pragma unroll 4
        for (int v = 0; v < NV; v++) {
            float fx = fxp[v * WW];
            #pragma unroll
            for (int r = 0; r < 8; r++) acc[r] += fx * s_fy[v][r];
        }
    }
    #pragma unroll
    for (int r = 0; r < 8; r++) {
        out_scat[(n * HH + y0 + r) * WW + x] = acc[r];
        uint16_t v = __half_as_ushort(__float2half_rn(acc[r]));
        int base = n * NS + 0 * CS + (y0 + r + 1) * 128;
        #pragma unroll
        for (int kx = 0; kx < 3; kx++) {
            int xq = x + 1 - kx;
            if (xq >= 0 && xq < 128) g_Xs[kx * KXS + base + xq] = v;
        }
    }
}

// ---------------- HMMA conv kernel: CTA = (row, ch-half) -------------------
// A tile k-major [128 rows(k*2+h)][128B], cp.async-staged. ldmatrix.trans.
// dyn smem: A0 16K | A1 16K | B0 16K | B1 16K = 64KB. 2 CTAs/SM.
#define DSMEM_BYTES (65536 + 1024)

__global__ void __launch_bounds__(256, 2)
k_conv_mma(const float* __restrict__ b1, const float* __restrict__ w2,
           float* __restrict__ outp) {
    extern __shared__ char dsm[];
    __shared__ int   s_off[KPAD];
    __shared__ float s_b1[CMID / 2];
    __shared__ float s_w2[2 * CMID / 2];
    __shared__ float s_part[HH * 2];

    const int tid  = threadIdx.x;
    const int wid  = tid >> 5;
    const int lane = tid & 31;
    const int gid  = lane >> 2;       // 0..7
    const int tq   = lane & 3;        // 0..3
    const int wm   = wid >> 2;        // 0..1 (px half: 64 px)
    const int wn   = wid & 3;         // 0..3 (32 ch each)
    const int row  = blockIdx.x >> 1;
    const int ch   = blockIdx.x & 1;  // channel half
    const int n = row >> 7;
    const int y = row & 127;
    const int chbase = ch * 128;

    const uint32_t sbu = smem_u32(dsm);
    const uint32_t pad = (1024u - (sbu & 1023u)) & 1023u;
    const uint32_t base = sbu + pad;
    // A buffers: +buf*16384 ; B buffers: +32768 + buf*16384

    for (int i = tid; i < 128; i += 256) {
        s_b1[i] = b1[chbase + i];
        s_w2[i] = w2[chbase + i];
        s_w2[128 + i] = w2[CMID + chbase + i];
    }
    s_part[tid] = 0.f;
    for (int k = tid; k < KPAD; k += 256) {
        int off = -1;
        if (k < KREAL) {
            int ci = k / 9, pos = k - ci * 9;
            int ky = pos / 3, kx = pos - ky * 3;
            off = kx * KXS + ci * CS + ky * 128;
        }
        s_off[k] = off;
    }

    float acc[4][4][4];
    #pragma unroll
    for (int mt = 0; mt < 4; mt++)
        #pragma unroll
        for (int nt = 0; nt < 4; nt++)
            #pragma unroll
            for (int r = 0; r < 4; r++) acc[mt][nt][r] = 0.f;

    const int xbase = n * NS + y * 128;

    // ldmatrix.trans lane addressing for A (k-major tile)
    const int g8 = lane >> 3;                  // matrix 0..3
    const int j8 = lane & 7;                   // k-row within matrix
    const int koff8 = (g8 >> 1) * 8;
    const int clane = g8 & 1;                  // px block (0 or +8)
    const int rbase = (j8 + koff8) * 2 + wm;   // smem row for ks=0
    // B fragment addressing (unchanged)
    const int brow = lane & 7;
    const int bcolsel = ((lane >> 3) & 1) * 16;

    // A staging: per thread 4 cp.async 16B identity copies
#define STAGE_A(k0, aA)                                                        \
    do {                                                                       \
        _Pragma("unroll")                                                      \
        for (int t = 0; t < 4; t++) {                                          \
            int idx = tid + t * 256;                                           \
            int rowi = idx >> 3;               /* 0..127 = k*2+h */            \
            int c8 = idx & 7;                                                  \
            int k = rowi >> 1, h = rowi & 1;                                   \
            int off = s_off[(k0) + k];                                         \
            uint32_t sz = (off >= 0) ? 16u : 0u;                               \
            const uint16_t* src = g_Xs + (xbase + (off >= 0 ? off : 0)         \
                                          + h * 64 + c8 * 8);                  \
            uint32_t dst = (aA) + rowi * 128 + ((c8 ^ (rowi & 7)) << 4);       \
            CP_ASYNC16Z(dst, src, sz);                                         \
        }                                                                      \
    } while (0)

#define STAGE_B(c, aB)                                                         \
    do {                                                                       \
        const char* src = (const char*)(g_wBh4 + (c) * 2048 + ch * 1024);      \
        _Pragma("unroll")                                                      \
        for (int i = 0; i < 4; i++) {                                          \
            int gi = tid + i * 256;                                            \
            CP_ASYNC16((aB) + gi * 16, src + gi * 16);                         \
        }                                                                      \
    } while (0)

    __syncthreads();
    STAGE_A(0, base);
    STAGE_B(0, base + 32768u);
    CP_COMMIT();
    CP_WAIT0();
    __syncthreads();

    for (int c = 0; c < NCH; c++) {
        const int cur = c & 1;
        const uint32_t aA = base + (uint32_t)cur * 16384u;
        const uint32_t aB = base + 32768u + (uint32_t)cur * 16384u;

        if (c < NCH - 1) {
            const int nxt = cur ^ 1;
            STAGE_A((c + 1) * CHUNK, base + (uint32_t)nxt * 16384u);
            STAGE_B(c + 1, base + 32768u + (uint32_t)nxt * 16384u);
            CP_COMMIT();
        }

        const int nks = (c == NCH - 1) ? 1 : 4;
        #pragma unroll
        for (int ks = 0; ks < 4; ks++) {
            if (ks >= nks) break;
            const int kcol = ks * 32;          // byte col of k-step for B
            uint32_t Af[4][4];
            #pragma unroll
            for (int mt = 0; mt < 4; mt++) {
                int r0 = rbase + ks * 32;      // smem row
                int chunk = mt * 2 + clane;
                uint32_t ad = aA + (uint32_t)(r0 * 128 + ((chunk ^ (r0 & 7)) << 4));
                ldm_x4_trans(Af[mt], ad);
            }
            uint32_t Bf[4][2];
            #pragma unroll
            for (int nt = 0; nt < 4; nt++) {
                int rowb = wn * 32 + nt * 8 + brow;
                int colb = kcol + bcolsel;
                uint32_t bd = aB + (uint32_t)(rowb * 128 + (colb ^ ((rowb & 7) * 16)));
                ldm_x2(Bf[nt], bd);
            }
            #pragma unroll
            for (int nt = 0; nt < 4; nt++)
                #pragma unroll
                for (int mt = 0; mt < 4; mt++)
                    mma_fp16(acc[mt][nt], Af[mt], Bf[nt]);
        }
        CP_WAIT0();
        __syncthreads();
    }

    // epilogue: relu(D + b1) -> partial 1x1 conv, reduce in smem, atomicAdd gmem
    #pragma unroll
    for (int mt = 0; mt < 4; mt++) {
        #pragma unroll
        for (int half = 0; half < 2; half++) {
            float s0 = 0.f, s1 = 0.f;
            #pragma unroll
            for (int nt = 0; nt < 4; nt++) {
                int cl = wn * 32 + nt * 8 + tq * 2;       // local ch 0..127
                float h0 = fmaxf(acc[mt][nt][half * 2 + 0] + s_b1[cl], 0.f);
                float h1 = fmaxf(acc[mt][nt][half * 2 + 1] + s_b1[cl + 1], 0.f);
                s0 += h0 * s_w2[cl] + h1 * s_w2[cl + 1];
                s1 += h0 * s_w2[128 + cl] + h1 * s_w2[128 + cl + 1];
            }
            s0 += __shfl_xor_sync(0xffffffffu, s0, 1);
            s0 += __shfl_xor_sync(0xffffffffu, s0, 2);
            s1 += __shfl_xor_sync(0xffffffffu, s1, 1);
            s1 += __shfl_xor_sync(0xffffffffu, s1, 2);
            if (tq == 0) {
                int px = wm * 64 + mt * 16 + half * 8 + gid;
                atomicAdd(&s_part[px * 2 + 0], s0);
                atomicAdd(&s_part[px * 2 + 1], s1);
            }
        }
    }
    __syncthreads();
    {
        int px = tid >> 1, o = tid & 1;
        atomicAdd(&outp[((n * 2 + o) * HH + y) * WW + px], s_part[px * 2 + o]);
    }
}

// ---------------- launch ----------------
extern "C" void kernel_launch(void* const* d_in, const int* in_sizes, int n_in,
                              void* d_out, int out_size) {
    const float* contour = (const float*)d_in[0];
    const float* feature = (const float*)d_in[1];
    const int*   batchi  = (const int*)d_in[2];
    const float* w1      = (const float*)d_in[3];
    const float* b1      = (const float*)d_in[4];
    const float* w2      = (const float*)d_in[5];
    const float* b2      = (const float*)d_in[6];
    float* out = (float*)d_out;
    float* out_scat = out + NIMG * 2 * HH * WW;

    static int attr_set = 0;
    if (!attr_set) {
        cudaFuncSetAttribute(k_conv_mma,
                             cudaFuncAttributeMaxDynamicSharedMemorySize,
                             DSMEM_BYTES);
        attr_set = 1;
    }

    k_prep1<<<NV * NC + 1, 128>>>(contour, batchi);
    k_prep2<<<FILL_BLOCKS + ZERO_BLOCKS + WS_BLOCKS + OINIT_BLOCKS, 256>>>(
        feature, w1, b2, out);
    k_scatter<<<dim3(HH / 8, NIMG), 128>>>(out_scat);
    k_conv_mma<<<2048, 256, DSMEM_BYTES>>>(b1, w2, out);
}